// round 1
// baseline (speedup 1.0000x reference)
#include <cuda_runtime.h>
#include <cuda_bf16.h>
#include <math.h>

// ---------------- static scratch (no allocation allowed) ----------------
#define N_CAP 65536
#define E_CAP (1 << 20)

__device__ float g_bufA[(size_t)N_CAP * 256];
__device__ float g_bufB[(size_t)N_CAP * 256];
__device__ float g_als[N_CAP * 4];
__device__ float g_ald[N_CAP * 4];
__device__ int   g_rowptr[N_CAP + 1];
__device__ int   g_wptr[N_CAP];
__device__ int   g_srcs[E_CAP];
__device__ int   g_bsum[80];
__device__ int   g_boff[80];

// ---------------- CSR build ----------------
__global__ void k_init_counts(int n) {
    int i = blockIdx.x * blockDim.x + threadIdx.x;
    if (i < n) g_wptr[i] = 1;  // self-loop pre-counted
}

__global__ void k_count(const int* __restrict__ ei, int e) {
    int t = blockIdx.x * blockDim.x + threadIdx.x;
    if (t < e) atomicAdd(&g_wptr[ei[e + t]], 1);
}

__global__ void k_scan1(int n) {
    __shared__ int sm[1024];
    int t = threadIdx.x;
    int i = blockIdx.x * 1024 + t;
    int v = (i < n) ? g_wptr[i] : 0;
    sm[t] = v;
    __syncthreads();
    for (int off = 1; off < 1024; off <<= 1) {
        int x = (t >= off) ? sm[t - off] : 0;
        __syncthreads();
        sm[t] += x;
        __syncthreads();
    }
    if (i < n) g_rowptr[i + 1] = sm[t];
    if (t == 1023) g_bsum[blockIdx.x] = sm[1023];
}

__global__ void k_scan2(int nb) {
    if (threadIdx.x == 0) {
        int acc = 0;
        for (int i = 0; i < nb; i++) { int v = g_bsum[i]; g_boff[i] = acc; acc += v; }
    }
}

__global__ void k_scan3(int n) {
    int t = threadIdx.x;
    int i = blockIdx.x * 1024 + t;
    if (i < n) g_rowptr[i + 1] += g_boff[blockIdx.x];
    if (i == 0) g_rowptr[0] = 0;
}

__global__ void k_copyw(int n) {
    int i = blockIdx.x * blockDim.x + threadIdx.x;
    if (i < n) g_wptr[i] = g_rowptr[i];
}

__global__ void k_scatter(const int* __restrict__ ei, int e, int n) {
    int t = blockIdx.x * blockDim.x + threadIdx.x;
    if (t < e) {
        int src = ei[t];
        int dst = ei[e + t];
        int pos = atomicAdd(&g_wptr[dst], 1);
        g_srcs[pos] = src;
    } else if (t < e + n) {
        int i = t - e;
        int pos = atomicAdd(&g_wptr[i], 1);
        g_srcs[pos] = i;  // self loop
    }
}

// ---------------- fp32 tiled GEMM: C[n,M] = A[n,K] @ B[K,M] ----------------
// K multiple of 16, M multiple of 64. Only n-rows need guarding.
__global__ __launch_bounds__(256) void k_gemm(const float* __restrict__ A,
                                              const float* __restrict__ B,
                                              float* __restrict__ C,
                                              int n, int K, int M) {
    __shared__ float As[16][68];
    __shared__ float Bs[16][64];
    int tid = threadIdx.x;
    int tx = tid & 15, ty = tid >> 4;
    int r0 = blockIdx.y * 64;
    int c0 = blockIdx.x * 64;

    int arow = tid >> 2, aq = (tid & 3) * 4;
    int brow = tid >> 4, bq = (tid & 15) * 4;

    float acc[4][4];
#pragma unroll
    for (int i = 0; i < 4; i++)
#pragma unroll
        for (int j = 0; j < 4; j++) acc[i][j] = 0.f;

    for (int k0 = 0; k0 < K; k0 += 16) {
        float4 av = make_float4(0.f, 0.f, 0.f, 0.f);
        if (r0 + arow < n)
            av = *(const float4*)&A[(size_t)(r0 + arow) * K + k0 + aq];
        As[aq + 0][arow] = av.x;
        As[aq + 1][arow] = av.y;
        As[aq + 2][arow] = av.z;
        As[aq + 3][arow] = av.w;
        *(float4*)&Bs[brow][bq] = *(const float4*)&B[(size_t)(k0 + brow) * M + c0 + bq];
        __syncthreads();
#pragma unroll
        for (int kk = 0; kk < 16; kk++) {
            float4 a4 = *(float4*)&As[kk][ty * 4];
            float4 b4 = *(float4*)&Bs[kk][tx * 4];
            float a[4] = {a4.x, a4.y, a4.z, a4.w};
            float b[4] = {b4.x, b4.y, b4.z, b4.w};
#pragma unroll
            for (int i = 0; i < 4; i++)
#pragma unroll
                for (int j = 0; j < 4; j++) acc[i][j] += a[i] * b[j];
        }
        __syncthreads();
    }
#pragma unroll
    for (int i = 0; i < 4; i++) {
        int r = r0 + ty * 4 + i;
        if (r < n) {
#pragma unroll
            for (int j = 0; j < 4; j++)
                C[(size_t)r * M + c0 + tx * 4 + j] = acc[i][j];
        }
    }
}

// ---------------- per-node attention logits: one warp per node ----------------
__global__ void k_attn(const float* __restrict__ h, const float* __restrict__ a_s,
                       const float* __restrict__ a_d, int n, int H, int C) {
    int g = blockIdx.x * blockDim.x + threadIdx.x;
    int node = g >> 5, lane = g & 31;
    if (node >= n) return;
    int F = H * C;
    for (int hh = 0; hh < H; hh++) {
        float ps = 0.f, pd = 0.f;
        for (int c = lane; c < C; c += 32) {
            float v = h[(size_t)node * F + hh * C + c];
            ps += v * a_s[hh * C + c];
            pd += v * a_d[hh * C + c];
        }
#pragma unroll
        for (int o = 16; o; o >>= 1) {
            ps += __shfl_down_sync(0xffffffffu, ps, o);
            pd += __shfl_down_sync(0xffffffffu, pd, o);
        }
        if (lane == 0) {
            g_als[node * 4 + hh] = ps;
            g_ald[node * 4 + hh] = pd;
        }
    }
}

// ---------------- aggregation: one block per dst node ----------------
// blockDim = H*64 (256 for H=4, 64 for H=1)
__global__ __launch_bounds__(256) void k_agg(const float* __restrict__ h,
                                             const float* __restrict__ bias,
                                             float* __restrict__ out,
                                             int H, int apply_elu) {
    int d = blockIdx.x;
    int t = threadIdx.x;
    int F = blockDim.x;
    __shared__ float s_m[4], s_inv[4], s_ald[4];
    __shared__ int s_src[64];
    __shared__ float s_alpha[64 * 4];

    int r0 = g_rowptr[d];
    int deg = g_rowptr[d + 1] - r0;

    if (t < H) s_ald[t] = g_ald[d * 4 + t];

    if (t < 32) {
        float m[4], sa[4], ad[4];
#pragma unroll
        for (int hh = 0; hh < 4; hh++) { m[hh] = -1e30f; sa[hh] = 0.f; ad[hh] = 0.f; }
        for (int hh = 0; hh < H; hh++) ad[hh] = g_ald[d * 4 + hh];
        for (int j = t; j < deg; j += 32) {
            int src = g_srcs[r0 + j];
            for (int hh = 0; hh < H; hh++) {
                float l = g_als[src * 4 + hh] + ad[hh];
                l = (l < 0.f) ? 0.2f * l : l;
                float nm = fmaxf(m[hh], l);
                sa[hh] = sa[hh] * __expf(m[hh] - nm) + __expf(l - nm);
                m[hh] = nm;
            }
        }
#pragma unroll
        for (int o = 16; o; o >>= 1) {
            for (int hh = 0; hh < H; hh++) {
                float mo = __shfl_down_sync(0xffffffffu, m[hh], o);
                float so = __shfl_down_sync(0xffffffffu, sa[hh], o);
                float nm = fmaxf(m[hh], mo);
                sa[hh] = sa[hh] * __expf(m[hh] - nm) + so * __expf(mo - nm);
                m[hh] = nm;
            }
        }
        if (t == 0) {
            for (int hh = 0; hh < H; hh++) {
                s_m[hh] = m[hh];
                s_inv[hh] = 1.f / (sa[hh] + 1e-16f);
            }
        }
    }
    __syncthreads();

    int head = t >> 6;
    float acc = 0.f;
    for (int base = 0; base < deg; base += 64) {
        int cn = min(64, deg - base);
        if (t < cn) s_src[t] = g_srcs[r0 + base + t];
        __syncthreads();
        if (t < cn * H) {
            int j = t / H, hh = t - j * H;
            int src = s_src[j];
            float l = g_als[src * 4 + hh] + s_ald[hh];
            l = (l < 0.f) ? 0.2f * l : l;
            s_alpha[(j << 2) + hh] = __expf(l - s_m[hh]) * s_inv[hh];
        }
        __syncthreads();
#pragma unroll 4
        for (int j = 0; j < cn; j++)
            acc += s_alpha[(j << 2) + head] * h[(size_t)s_src[j] * F + t];
        __syncthreads();
    }
    float v = acc + bias[t];
    if (apply_elu) v = (v > 0.f) ? v : expm1f(v);
    out[(size_t)d * F + t] = v;
}

// ---------------- launcher ----------------
extern "C" void kernel_launch(void* const* d_in, const int* in_sizes, int n_in,
                              void* d_out, int out_size) {
    const float* x   = (const float*)d_in[0];
    const int*   ei  = (const int*)d_in[1];
    const float* W1  = (const float*)d_in[2];
    const float* as1 = (const float*)d_in[3];
    const float* ad1 = (const float*)d_in[4];
    const float* b1  = (const float*)d_in[5];
    const float* W2  = (const float*)d_in[6];
    const float* as2 = (const float*)d_in[7];
    const float* ad2 = (const float*)d_in[8];
    const float* b2  = (const float*)d_in[9];
    const float* W3  = (const float*)d_in[10];
    const float* as3 = (const float*)d_in[11];
    const float* ad3 = (const float*)d_in[12];
    const float* b3  = (const float*)d_in[13];
    float* out = (float*)d_out;

    int n = in_sizes[0] / 256;   // 50000
    int e = in_sizes[1] / 2;     // 320000

    float *bufA, *bufB;
    cudaGetSymbolAddress((void**)&bufA, g_bufA);
    cudaGetSymbolAddress((void**)&bufB, g_bufB);

    // --- build CSR by destination ---
    k_init_counts<<<(n + 255) / 256, 256>>>(n);
    k_count<<<(e + 255) / 256, 256>>>(ei, e);
    int nb1 = (n + 1023) / 1024;
    k_scan1<<<nb1, 1024>>>(n);
    k_scan2<<<1, 32>>>(nb1);
    k_scan3<<<nb1, 1024>>>(n);
    k_copyw<<<(n + 255) / 256, 256>>>(n);
    k_scatter<<<(e + n + 255) / 256, 256>>>(ei, e, n);

    int nrb = (n + 63) / 64;            // GEMM row blocks
    int nwb = (n * 32 + 255) / 256;     // attn warp blocks

    // --- layer 1: x[ n,256 ] @ W1[256,256] ---
    k_gemm<<<dim3(4, nrb), 256>>>(x, W1, bufA, n, 256, 256);
    k_attn<<<nwb, 256>>>(bufA, as1, ad1, n, 4, 64);
    k_agg<<<n, 256>>>(bufA, b1, bufB, 4, 1);

    // --- layer 2 ---
    k_gemm<<<dim3(4, nrb), 256>>>(bufB, W2, bufA, n, 256, 256);
    k_attn<<<nwb, 256>>>(bufA, as2, ad2, n, 4, 64);
    k_agg<<<n, 256>>>(bufA, b2, bufB, 4, 1);

    // --- layer 3: [n,256] @ W3[256,64], H=1, no ELU, mean over 1 head = identity ---
    k_gemm<<<dim3(1, nrb), 256>>>(bufB, W3, bufA, n, 256, 64);
    k_attn<<<nwb, 256>>>(bufA, as3, ad3, n, 1, 64);
    k_agg<<<n, 64>>>(bufA, b3, out, 1, 0);
}

// round 2
// speedup vs baseline: 1.2228x; 1.2228x over previous
#include <cuda_runtime.h>
#include <cuda_bf16.h>
#include <math.h>
#include <stdint.h>

// ---------------- static scratch (no allocation allowed) ----------------
#define N_CAP 65536
#define E_CAP (1 << 20)

__device__ float g_bufA[(size_t)N_CAP * 256];
__device__ float g_bufB[(size_t)N_CAP * 256];
__device__ float g_als[N_CAP * 4];
__device__ float g_ald[N_CAP * 4];
__device__ int   g_rowptr[N_CAP + 1];
__device__ int   g_wptr[N_CAP];
__device__ int   g_srcs[E_CAP];
__device__ int   g_bsum[80];
__device__ int   g_boff[80];

// ---------------- CSR build ----------------
__global__ void k_init_counts(int n) {
    int i = blockIdx.x * blockDim.x + threadIdx.x;
    if (i < n) g_wptr[i] = 1;  // self-loop pre-counted
}

__global__ void k_count(const int* __restrict__ ei, int e) {
    int t = blockIdx.x * blockDim.x + threadIdx.x;
    if (t < e) atomicAdd(&g_wptr[ei[e + t]], 1);
}

__global__ void k_scan1(int n) {
    __shared__ int sm[1024];
    int t = threadIdx.x;
    int i = blockIdx.x * 1024 + t;
    int v = (i < n) ? g_wptr[i] : 0;
    sm[t] = v;
    __syncthreads();
    for (int off = 1; off < 1024; off <<= 1) {
        int x = (t >= off) ? sm[t - off] : 0;
        __syncthreads();
        sm[t] += x;
        __syncthreads();
    }
    if (i < n) g_rowptr[i + 1] = sm[t];
    if (t == 1023) g_bsum[blockIdx.x] = sm[1023];
}

__global__ void k_scan2(int nb) {
    if (threadIdx.x == 0) {
        int acc = 0;
        for (int i = 0; i < nb; i++) { int v = g_bsum[i]; g_boff[i] = acc; acc += v; }
    }
}

__global__ void k_scan3(int n) {
    int t = threadIdx.x;
    int i = blockIdx.x * 1024 + t;
    if (i < n) g_rowptr[i + 1] += g_boff[blockIdx.x];
    if (i == 0) g_rowptr[0] = 0;
}

__global__ void k_copyw(int n) {
    int i = blockIdx.x * blockDim.x + threadIdx.x;
    if (i < n) g_wptr[i] = g_rowptr[i];
}

__global__ void k_scatter(const int* __restrict__ ei, int e, int n) {
    int t = blockIdx.x * blockDim.x + threadIdx.x;
    if (t < e) {
        int src = ei[t];
        int dst = ei[e + t];
        int pos = atomicAdd(&g_wptr[dst], 1);
        g_srcs[pos] = src;
    } else if (t < e + n) {
        int i = t - e;
        int pos = atomicAdd(&g_wptr[i], 1);
        g_srcs[pos] = i;  // self loop
    }
}

// ---------------- tf32 tensor-core GEMM ----------------
// C[n,M] = A[n,K] @ B[K,M].  K%32==0, M%64==0.
// Block tile 128x64, BK=32, 8 warps in 4x2, each warp 32x32 via m16n8k8 tf32.
__device__ __forceinline__ uint32_t f2tf(float f) {
    uint32_t r;
    asm("cvt.rna.tf32.f32 %0, %1;" : "=r"(r) : "f"(f));
    return r;
}

__global__ __launch_bounds__(256) void k_gemm_tc(const float* __restrict__ A,
                                                 const float* __restrict__ B,
                                                 float* __restrict__ C,
                                                 int n, int K, int M) {
    // pads chosen for conflict-free mma fragment reads:
    // A bank = (4*row + col) % 32 (pad 36), B bank = (8*k + n) % 32 (pad 72)
    __shared__ uint32_t As[128][36];
    __shared__ uint32_t Bs[32][72];

    int tid = threadIdx.x, lane = tid & 31, warp = tid >> 5;
    int wm = warp >> 1, wn = warp & 1;           // 4 x 2 warp grid
    int r0 = blockIdx.y * 128, c0 = blockIdx.x * 64;

    float acc[2][4][4];
#pragma unroll
    for (int mt = 0; mt < 2; mt++)
#pragma unroll
        for (int nt = 0; nt < 4; nt++)
#pragma unroll
            for (int i = 0; i < 4; i++) acc[mt][nt][i] = 0.f;

    int ar = tid >> 3, ac = (tid & 7) * 4;       // A: 4 rows/thread (stride 32)
    int br = tid >> 4, bc = (tid & 15) * 4;      // B: 2 rows/thread (stride 16)

    for (int k0 = 0; k0 < K; k0 += 32) {
#pragma unroll
        for (int i = 0; i < 4; i++) {
            int r = ar + 32 * i;
            float4 v = make_float4(0.f, 0.f, 0.f, 0.f);
            if (r0 + r < n) v = *(const float4*)&A[(size_t)(r0 + r) * K + k0 + ac];
            As[r][ac + 0] = f2tf(v.x);
            As[r][ac + 1] = f2tf(v.y);
            As[r][ac + 2] = f2tf(v.z);
            As[r][ac + 3] = f2tf(v.w);
        }
#pragma unroll
        for (int i = 0; i < 2; i++) {
            int r = br + 16 * i;
            float4 v = *(const float4*)&B[(size_t)(k0 + r) * M + c0 + bc];
            Bs[r][bc + 0] = f2tf(v.x);
            Bs[r][bc + 1] = f2tf(v.y);
            Bs[r][bc + 2] = f2tf(v.z);
            Bs[r][bc + 3] = f2tf(v.w);
        }
        __syncthreads();

#pragma unroll
        for (int ks = 0; ks < 4; ks++) {
            int kb = ks * 8;
            uint32_t a[2][4], b[4][2];
#pragma unroll
            for (int mt = 0; mt < 2; mt++) {
                int row = wm * 32 + mt * 16 + (lane >> 2);
                int col = kb + (lane & 3);
                a[mt][0] = As[row][col];
                a[mt][1] = As[row + 8][col];
                a[mt][2] = As[row][col + 4];
                a[mt][3] = As[row + 8][col + 4];
            }
#pragma unroll
            for (int nt = 0; nt < 4; nt++) {
                int nn = wn * 32 + nt * 8 + (lane >> 2);
                int kk = kb + (lane & 3);
                b[nt][0] = Bs[kk][nn];
                b[nt][1] = Bs[kk + 4][nn];
            }
#pragma unroll
            for (int mt = 0; mt < 2; mt++)
#pragma unroll
                for (int nt = 0; nt < 4; nt++) {
                    asm volatile(
                        "mma.sync.aligned.m16n8k8.row.col.f32.tf32.tf32.f32 "
                        "{%0,%1,%2,%3}, {%4,%5,%6,%7}, {%8,%9}, {%0,%1,%2,%3};"
                        : "+f"(acc[mt][nt][0]), "+f"(acc[mt][nt][1]),
                          "+f"(acc[mt][nt][2]), "+f"(acc[mt][nt][3])
                        : "r"(a[mt][0]), "r"(a[mt][1]), "r"(a[mt][2]), "r"(a[mt][3]),
                          "r"(b[nt][0]), "r"(b[nt][1]));
                }
        }
        __syncthreads();
    }

    // epilogue: c0,c1 at (row, 2c),(row, 2c+1); c2,c3 at row+8
#pragma unroll
    for (int mt = 0; mt < 2; mt++) {
        int row = r0 + wm * 32 + mt * 16 + (lane >> 2);
#pragma unroll
        for (int nt = 0; nt < 4; nt++) {
            int col = c0 + wn * 32 + nt * 8 + (lane & 3) * 2;
            if (row < n) {
                *(float2*)&C[(size_t)row * M + col] =
                    make_float2(acc[mt][nt][0], acc[mt][nt][1]);
            }
            if (row + 8 < n) {
                *(float2*)&C[(size_t)(row + 8) * M + col] =
                    make_float2(acc[mt][nt][2], acc[mt][nt][3]);
            }
        }
    }
}

// ---------------- per-node attention logits: one warp per node ----------------
__global__ void k_attn(const float* __restrict__ h, const float* __restrict__ a_s,
                       const float* __restrict__ a_d, int n, int H, int C) {
    int g = blockIdx.x * blockDim.x + threadIdx.x;
    int node = g >> 5, lane = g & 31;
    if (node >= n) return;
    int F = H * C;
    for (int hh = 0; hh < H; hh++) {
        float ps = 0.f, pd = 0.f;
        for (int c = lane; c < C; c += 32) {
            float v = h[(size_t)node * F + hh * C + c];
            ps += v * a_s[hh * C + c];
            pd += v * a_d[hh * C + c];
        }
#pragma unroll
        for (int o = 16; o; o >>= 1) {
            ps += __shfl_down_sync(0xffffffffu, ps, o);
            pd += __shfl_down_sync(0xffffffffu, pd, o);
        }
        if (lane == 0) {
            g_als[node * 4 + hh] = ps;
            g_ald[node * 4 + hh] = pd;
        }
    }
}

// ---------------- aggregation: one block per dst node ----------------
__global__ __launch_bounds__(256) void k_agg(const float* __restrict__ h,
                                             const float* __restrict__ bias,
                                             float* __restrict__ out,
                                             int H, int apply_elu) {
    int d = blockIdx.x;
    int t = threadIdx.x;
    int F = blockDim.x;
    __shared__ float s_m[4], s_inv[4], s_ald[4];
    __shared__ int s_src[64];
    __shared__ float s_alpha[64 * 4];

    int r0 = g_rowptr[d];
    int deg = g_rowptr[d + 1] - r0;

    if (t < H) s_ald[t] = g_ald[d * 4 + t];

    if (t < 32) {
        float m[4], sa[4], ad[4];
#pragma unroll
        for (int hh = 0; hh < 4; hh++) { m[hh] = -1e30f; sa[hh] = 0.f; ad[hh] = 0.f; }
        for (int hh = 0; hh < H; hh++) ad[hh] = g_ald[d * 4 + hh];
        for (int j = t; j < deg; j += 32) {
            int src = g_srcs[r0 + j];
            for (int hh = 0; hh < H; hh++) {
                float l = g_als[src * 4 + hh] + ad[hh];
                l = (l < 0.f) ? 0.2f * l : l;
                float nm = fmaxf(m[hh], l);
                sa[hh] = sa[hh] * __expf(m[hh] - nm) + __expf(l - nm);
                m[hh] = nm;
            }
        }
#pragma unroll
        for (int o = 16; o; o >>= 1) {
            for (int hh = 0; hh < H; hh++) {
                float mo = __shfl_down_sync(0xffffffffu, m[hh], o);
                float so = __shfl_down_sync(0xffffffffu, sa[hh], o);
                float nm = fmaxf(m[hh], mo);
                sa[hh] = sa[hh] * __expf(m[hh] - nm) + so * __expf(mo - nm);
                m[hh] = nm;
            }
        }
        if (t == 0) {
            for (int hh = 0; hh < H; hh++) {
                s_m[hh] = m[hh];
                s_inv[hh] = 1.f / (sa[hh] + 1e-16f);
            }
        }
    }
    __syncthreads();

    int head = t >> 6;
    float acc = 0.f;
    for (int base = 0; base < deg; base += 64) {
        int cn = min(64, deg - base);
        if (t < cn) s_src[t] = g_srcs[r0 + base + t];
        __syncthreads();
        if (t < cn * H) {
            int j = t / H, hh = t - j * H;
            int src = s_src[j];
            float l = g_als[src * 4 + hh] + s_ald[hh];
            l = (l < 0.f) ? 0.2f * l : l;
            s_alpha[(j << 2) + hh] = __expf(l - s_m[hh]) * s_inv[hh];
        }
        __syncthreads();
#pragma unroll 4
        for (int j = 0; j < cn; j++)
            acc += s_alpha[(j << 2) + head] * h[(size_t)s_src[j] * F + t];
        __syncthreads();
    }
    float v = acc + bias[t];
    if (apply_elu) v = (v > 0.f) ? v : expm1f(v);
    out[(size_t)d * F + t] = v;
}

// ---------------- launcher ----------------
extern "C" void kernel_launch(void* const* d_in, const int* in_sizes, int n_in,
                              void* d_out, int out_size) {
    const float* x   = (const float*)d_in[0];
    const int*   ei  = (const int*)d_in[1];
    const float* W1  = (const float*)d_in[2];
    const float* as1 = (const float*)d_in[3];
    const float* ad1 = (const float*)d_in[4];
    const float* b1  = (const float*)d_in[5];
    const float* W2  = (const float*)d_in[6];
    const float* as2 = (const float*)d_in[7];
    const float* ad2 = (const float*)d_in[8];
    const float* b2  = (const float*)d_in[9];
    const float* W3  = (const float*)d_in[10];
    const float* as3 = (const float*)d_in[11];
    const float* ad3 = (const float*)d_in[12];
    const float* b3  = (const float*)d_in[13];
    float* out = (float*)d_out;

    int n = in_sizes[0] / 256;   // 50000
    int e = in_sizes[1] / 2;     // 320000

    float *bufA, *bufB;
    cudaGetSymbolAddress((void**)&bufA, g_bufA);
    cudaGetSymbolAddress((void**)&bufB, g_bufB);

    // --- build CSR by destination ---
    k_init_counts<<<(n + 255) / 256, 256>>>(n);
    k_count<<<(e + 255) / 256, 256>>>(ei, e);
    int nb1 = (n + 1023) / 1024;
    k_scan1<<<nb1, 1024>>>(n);
    k_scan2<<<1, 32>>>(nb1);
    k_scan3<<<nb1, 1024>>>(n);
    k_copyw<<<(n + 255) / 256, 256>>>(n);
    k_scatter<<<(e + n + 255) / 256, 256>>>(ei, e, n);

    int nrb = (n + 127) / 128;          // GEMM row blocks (128 rows/block)
    int nwb = (n * 32 + 255) / 256;     // attn warp blocks

    // --- layer 1: x[n,256] @ W1[256,256] ---
    k_gemm_tc<<<dim3(4, nrb), 256>>>(x, W1, bufA, n, 256, 256);
    k_attn<<<nwb, 256>>>(bufA, as1, ad1, n, 4, 64);
    k_agg<<<n, 256>>>(bufA, b1, bufB, 4, 1);

    // --- layer 2 ---
    k_gemm_tc<<<dim3(4, nrb), 256>>>(bufB, W2, bufA, n, 256, 256);
    k_attn<<<nwb, 256>>>(bufA, as2, ad2, n, 4, 64);
    k_agg<<<n, 256>>>(bufA, b2, bufB, 4, 1);

    // --- layer 3: [n,256] @ W3[256,64], H=1, no ELU ---
    k_gemm_tc<<<dim3(1, nrb), 256>>>(bufB, W3, bufA, n, 256, 64);
    k_attn<<<nwb, 256>>>(bufA, as3, ad3, n, 1, 64);
    k_agg<<<n, 64>>>(bufA, b3, out, 1, 0);
}

// round 3
// speedup vs baseline: 1.4161x; 1.1580x over previous
#include <cuda_runtime.h>
#include <cuda_bf16.h>
#include <math.h>
#include <stdint.h>

// ---------------- static scratch (no allocation allowed) ----------------
#define N_CAP 65536
#define E_CAP (1 << 20)

__device__ float    g_bufA[(size_t)N_CAP * 256];   // fp32 h of current layer
__device__ uint32_t g_bufBt[(size_t)N_CAP * 256];  // tf32 agg output
__device__ uint32_t g_xt[(size_t)N_CAP * 256];     // tf32 input x
__device__ uint32_t g_w1t[65536];
__device__ uint32_t g_w2t[65536];
__device__ uint32_t g_w3t[16384];
__device__ float g_als[N_CAP * 4];
__device__ float g_ald[N_CAP * 4];
__device__ int   g_rowptr[N_CAP + 1];
__device__ int   g_wptr[N_CAP];
__device__ int   g_srcs[E_CAP];
__device__ int   g_bsum[80];

__device__ __forceinline__ uint32_t f2tf(float f) {
    uint32_t r;
    asm("cvt.rna.tf32.f32 %0, %1;" : "=r"(r) : "f"(f));
    return r;
}

// ---------------- preconvert + init ----------------
__global__ void k_pre(const float* __restrict__ x, const float* __restrict__ W1,
                      const float* __restrict__ W2, const float* __restrict__ W3,
                      int nx, int nw1, int nw2, int nw3, int n) {
    int i = blockIdx.x * blockDim.x + threadIdx.x;
    int stride = gridDim.x * blockDim.x;
    for (int j = i; j < nx; j += stride) g_xt[j] = f2tf(x[j]);
    for (int j = i; j < nw1; j += stride) g_w1t[j] = f2tf(W1[j]);
    for (int j = i; j < nw2; j += stride) g_w2t[j] = f2tf(W2[j]);
    for (int j = i; j < nw3; j += stride) g_w3t[j] = f2tf(W3[j]);
    for (int j = i; j < n; j += stride) g_wptr[j] = 1;  // self-loop pre-count
}

// ---------------- CSR build ----------------
__global__ void k_count(const int* __restrict__ ei, int e) {
    int t = blockIdx.x * blockDim.x + threadIdx.x;
    if (t < e) atomicAdd(&g_wptr[ei[e + t]], 1);
}

__global__ void k_scan1(int n) {
    __shared__ int sm[1024];
    int t = threadIdx.x;
    int i = blockIdx.x * 1024 + t;
    int v = (i < n) ? g_wptr[i] : 0;
    sm[t] = v;
    __syncthreads();
    for (int off = 1; off < 1024; off <<= 1) {
        int x = (t >= off) ? sm[t - off] : 0;
        __syncthreads();
        sm[t] += x;
        __syncthreads();
    }
    if (i < n) g_rowptr[i + 1] = sm[t];
    if (t == 1023) g_bsum[blockIdx.x] = sm[1023];
}

// merged: cross-block offsets + add + write wptr(=rowptr) for scatter
__global__ void k_scan3m(int n) {
    __shared__ int s_off;
    int t = threadIdx.x, b = blockIdx.x;
    if (t < 32) {
        int acc = 0;
        for (int i = t; i < b; i += 32) acc += g_bsum[i];
#pragma unroll
        for (int o = 16; o; o >>= 1) acc += __shfl_down_sync(0xffffffffu, acc, o);
        if (t == 0) s_off = acc;
    }
    __syncthreads();
    int i = b * 1024 + t;
    if (i < n) {
        int v = g_rowptr[i + 1] + s_off;
        g_rowptr[i + 1] = v;
        if (i + 1 < n) g_wptr[i + 1] = v;
    }
    if (i == 0) { g_rowptr[0] = 0; g_wptr[0] = 0; }
}

__global__ void k_scatter(const int* __restrict__ ei, int e, int n) {
    int t = blockIdx.x * blockDim.x + threadIdx.x;
    if (t < e) {
        int src = ei[t];
        int dst = ei[e + t];
        int pos = atomicAdd(&g_wptr[dst], 1);
        g_srcs[pos] = src;
    } else if (t < e + n) {
        int i = t - e;
        int pos = atomicAdd(&g_wptr[i], 1);
        g_srcs[pos] = i;  // self loop
    }
}

// ---------------- cp.async helpers ----------------
__device__ __forceinline__ void cp16(uint32_t dst, const void* src, int bytes) {
    asm volatile("cp.async.cg.shared.global [%0], [%1], 16, %2;"
                 :: "r"(dst), "l"(src), "r"(bytes));
}
__device__ __forceinline__ void cp_commit() { asm volatile("cp.async.commit_group;"); }
template <int NN> __device__ __forceinline__ void cp_wait() {
    asm volatile("cp.async.wait_group %0;" :: "n"(NN));
}

// ---------------- tf32 tensor-core GEMM + fused attention logits ----------------
// C[n,M] = A[n,K] @ B[K,M], A/B already tf32. Tile 128x128, BK=16.
// 8 warps = 4 (rows of 32) x 2 (cols of 64 = one head each).
// Epilogue also computes g_als/g_ald (dot with a_s/a_d per head).
__global__ __launch_bounds__(256) void k_gemm_tc(const uint32_t* __restrict__ A,
                                                 const uint32_t* __restrict__ B,
                                                 float* __restrict__ C,
                                                 const float* __restrict__ a_s,
                                                 const float* __restrict__ a_d,
                                                 int n, int K, int M) {
    __shared__ uint32_t As[2][128][20];   // 16 cols used, pad 4
    __shared__ uint32_t Bs[2][16][136];   // 128 cols used, pad 8
    __shared__ float s_als[128][2], s_ald[128][2];
    __shared__ float s_as[128], s_ad[128];

    int tid = threadIdx.x, lane = tid & 31, warp = tid >> 5;
    int wm = warp >> 1, wn = warp & 1;
    int r0 = blockIdx.y * 128, c0 = blockIdx.x * 128;

    uint32_t as_base = (uint32_t)__cvta_generic_to_shared(&As[0][0][0]);
    uint32_t bs_base = (uint32_t)__cvta_generic_to_shared(&Bs[0][0][0]);

    // stage a_s/a_d slice for this block's columns
    if (tid < 128 && c0 + tid < M) {
        s_as[tid] = a_s[c0 + tid];
        s_ad[tid] = a_d[c0 + tid];
    }

    float acc[2][8][4];
#pragma unroll
    for (int mt = 0; mt < 2; mt++)
#pragma unroll
        for (int nt = 0; nt < 8; nt++)
#pragma unroll
            for (int i = 0; i < 4; i++) acc[mt][nt][i] = 0.f;

    int KT = K >> 4;

#define LOAD_TILE(KT_IDX, BUF)                                                      \
    {                                                                               \
        int k0 = (KT_IDX) << 4;                                                     \
        _Pragma("unroll")                                                           \
        for (int i = 0; i < 2; i++) {                                               \
            int row = (tid >> 2) + 64 * i;                                          \
            int ac = (tid & 3) * 4;                                                 \
            int gr = r0 + row;                                                      \
            const uint32_t* src = A + (size_t)(gr < n ? gr : 0) * K + k0 + ac;      \
            cp16(as_base + (((BUF) * 128 + row) * 20 + ac) * 4, src,                \
                 gr < n ? 16 : 0);                                                  \
        }                                                                           \
        _Pragma("unroll")                                                           \
        for (int i = 0; i < 2; i++) {                                               \
            int rr = tid >> 4;                                                      \
            int bc = (tid & 15) * 8 + i * 4;                                        \
            int gc = c0 + bc;                                                       \
            const uint32_t* src = B + (size_t)(k0 + rr) * M + (gc < M ? gc : 0);    \
            cp16(bs_base + (((BUF) * 16 + rr) * 136 + bc) * 4, src,                 \
                 gc < M ? 16 : 0);                                                  \
        }                                                                           \
    }

    LOAD_TILE(0, 0);
    cp_commit();

    for (int kt = 0; kt < KT; kt++) {
        int buf = kt & 1;
        if (kt + 1 < KT) {
            LOAD_TILE(kt + 1, buf ^ 1);
            cp_commit();
            cp_wait<1>();
        } else {
            cp_wait<0>();
        }
        __syncthreads();

#pragma unroll
        for (int ks = 0; ks < 2; ks++) {
            int kb = ks * 8;
            uint32_t a[2][4], b[8][2];
#pragma unroll
            for (int mt = 0; mt < 2; mt++) {
                int row = wm * 32 + mt * 16 + (lane >> 2);
                int col = kb + (lane & 3);
                a[mt][0] = As[buf][row][col];
                a[mt][1] = As[buf][row + 8][col];
                a[mt][2] = As[buf][row][col + 4];
                a[mt][3] = As[buf][row + 8][col + 4];
            }
#pragma unroll
            for (int nt = 0; nt < 8; nt++) {
                int nn = wn * 64 + nt * 8 + (lane >> 2);
                int kk = kb + (lane & 3);
                b[nt][0] = Bs[buf][kk][nn];
                b[nt][1] = Bs[buf][kk + 4][nn];
            }
#pragma unroll
            for (int mt = 0; mt < 2; mt++)
#pragma unroll
                for (int nt = 0; nt < 8; nt++) {
                    asm volatile(
                        "mma.sync.aligned.m16n8k8.row.col.f32.tf32.tf32.f32 "
                        "{%0,%1,%2,%3}, {%4,%5,%6,%7}, {%8,%9}, {%0,%1,%2,%3};"
                        : "+f"(acc[mt][nt][0]), "+f"(acc[mt][nt][1]),
                          "+f"(acc[mt][nt][2]), "+f"(acc[mt][nt][3])
                        : "r"(a[mt][0]), "r"(a[mt][1]), "r"(a[mt][2]), "r"(a[mt][3]),
                          "r"(b[nt][0]), "r"(b[nt][1]));
                }
        }
        __syncthreads();
    }

    // ---- fused attention-logit epilogue + C store ----
    bool colok = (c0 + wn * 64) < M;   // whole 64-wide warp column valid?
    int hh = (c0 >> 6) + wn;           // head index of this warp's columns

    if (colok) {
#pragma unroll
        for (int mt = 0; mt < 2; mt++) {
#pragma unroll
            for (int rr = 0; rr < 2; rr++) {
                float ps = 0.f, pd = 0.f;
#pragma unroll
                for (int nt = 0; nt < 8; nt++)
#pragma unroll
                    for (int q = 0; q < 2; q++) {
                        int lc = nt * 8 + (lane & 3) * 2 + q;
                        float v = acc[mt][nt][rr * 2 + q];
                        ps = fmaf(v, s_as[wn * 64 + lc], ps);
                        pd = fmaf(v, s_ad[wn * 64 + lc], pd);
                    }
                ps += __shfl_down_sync(0xffffffffu, ps, 1);
                ps += __shfl_down_sync(0xffffffffu, ps, 2);
                pd += __shfl_down_sync(0xffffffffu, pd, 1);
                pd += __shfl_down_sync(0xffffffffu, pd, 2);
                if ((lane & 3) == 0) {
                    int rl = wm * 32 + mt * 16 + (lane >> 2) + rr * 8;
                    s_als[rl][wn] = ps;
                    s_ald[rl][wn] = pd;
                }
            }
        }
        // store C
#pragma unroll
        for (int mt = 0; mt < 2; mt++) {
            int row = r0 + wm * 32 + mt * 16 + (lane >> 2);
#pragma unroll
            for (int nt = 0; nt < 8; nt++) {
                int col = c0 + wn * 64 + nt * 8 + (lane & 3) * 2;
                if (row < n)
                    *(float2*)&C[(size_t)row * M + col] =
                        make_float2(acc[mt][nt][0], acc[mt][nt][1]);
                if (row + 8 < n)
                    *(float2*)&C[(size_t)(row + 8) * M + col] =
                        make_float2(acc[mt][nt][2], acc[mt][nt][3]);
            }
        }
    }
    __syncthreads();

    if (tid < 128) {
        int row = r0 + tid;
        if (row < n) {
            int hb = c0 >> 6;
            g_als[row * 4 + hb] = s_als[tid][0];
            g_ald[row * 4 + hb] = s_ald[tid][0];
            if (c0 + 64 < M) {
                g_als[row * 4 + hb + 1] = s_als[tid][1];
                g_ald[row * 4 + hb + 1] = s_ald[tid][1];
            }
        }
    }
}

// ---------------- aggregation: one block per dst node ----------------
// out_t != nullptr -> write tf32 (feeds next GEMM); else write fp32 to out.
__global__ __launch_bounds__(256) void k_agg(const float* __restrict__ h,
                                             const float* __restrict__ bias,
                                             float* __restrict__ out,
                                             uint32_t* __restrict__ out_t,
                                             int H, int apply_elu) {
    int d = blockIdx.x;
    int t = threadIdx.x;
    int F = blockDim.x;
    __shared__ float s_m[4], s_inv[4], s_ald[4];
    __shared__ int s_src[64];
    __shared__ float s_alpha[64 * 4];

    int r0 = g_rowptr[d];
    int deg = g_rowptr[d + 1] - r0;

    if (t < H) s_ald[t] = g_ald[d * 4 + t];

    if (t < 32) {
        float m[4], sa[4], ad[4];
#pragma unroll
        for (int hh = 0; hh < 4; hh++) { m[hh] = -1e30f; sa[hh] = 0.f; ad[hh] = 0.f; }
        for (int hh = 0; hh < H; hh++) ad[hh] = g_ald[d * 4 + hh];
        for (int j = t; j < deg; j += 32) {
            int src = g_srcs[r0 + j];
            for (int hh = 0; hh < H; hh++) {
                float l = g_als[src * 4 + hh] + ad[hh];
                l = (l < 0.f) ? 0.2f * l : l;
                float nm = fmaxf(m[hh], l);
                sa[hh] = sa[hh] * __expf(m[hh] - nm) + __expf(l - nm);
                m[hh] = nm;
            }
        }
#pragma unroll
        for (int o = 16; o; o >>= 1) {
            for (int hh = 0; hh < H; hh++) {
                float mo = __shfl_down_sync(0xffffffffu, m[hh], o);
                float so = __shfl_down_sync(0xffffffffu, sa[hh], o);
                float nm = fmaxf(m[hh], mo);
                sa[hh] = sa[hh] * __expf(m[hh] - nm) + so * __expf(mo - nm);
                m[hh] = nm;
            }
        }
        if (t == 0) {
            for (int hh = 0; hh < H; hh++) {
                s_m[hh] = m[hh];
                s_inv[hh] = 1.f / (sa[hh] + 1e-16f);
            }
        }
    }
    __syncthreads();

    int head = t >> 6;
    float acc = 0.f;
    for (int base = 0; base < deg; base += 64) {
        int cn = min(64, deg - base);
        if (t < cn) s_src[t] = g_srcs[r0 + base + t];
        __syncthreads();
        if (t < cn * H) {
            int j = t / H, hh = t - j * H;
            int src = s_src[j];
            float l = g_als[src * 4 + hh] + s_ald[hh];
            l = (l < 0.f) ? 0.2f * l : l;
            s_alpha[(j << 2) + hh] = __expf(l - s_m[hh]) * s_inv[hh];
        }
        __syncthreads();
#pragma unroll 4
        for (int j = 0; j < cn; j++)
            acc += s_alpha[(j << 2) + head] * h[(size_t)s_src[j] * F + t];
        __syncthreads();
    }
    float v = acc + bias[t];
    if (apply_elu) v = (v > 0.f) ? v : expm1f(v);
    if (out_t) out_t[(size_t)d * F + t] = f2tf(v);
    else out[(size_t)d * F + t] = v;
}

// ---------------- launcher ----------------
extern "C" void kernel_launch(void* const* d_in, const int* in_sizes, int n_in,
                              void* d_out, int out_size) {
    const float* x   = (const float*)d_in[0];
    const int*   ei  = (const int*)d_in[1];
    const float* W1  = (const float*)d_in[2];
    const float* as1 = (const float*)d_in[3];
    const float* ad1 = (const float*)d_in[4];
    const float* b1  = (const float*)d_in[5];
    const float* W2  = (const float*)d_in[6];
    const float* as2 = (const float*)d_in[7];
    const float* ad2 = (const float*)d_in[8];
    const float* b2  = (const float*)d_in[9];
    const float* W3  = (const float*)d_in[10];
    const float* as3 = (const float*)d_in[11];
    const float* ad3 = (const float*)d_in[12];
    const float* b3  = (const float*)d_in[13];
    float* out = (float*)d_out;

    int n = in_sizes[0] / 256;   // 50000
    int e = in_sizes[1] / 2;     // 320000

    float *bufA;
    uint32_t *bufBt, *xt, *w1t, *w2t, *w3t;
    cudaGetSymbolAddress((void**)&bufA, g_bufA);
    cudaGetSymbolAddress((void**)&bufBt, g_bufBt);
    cudaGetSymbolAddress((void**)&xt, g_xt);
    cudaGetSymbolAddress((void**)&w1t, g_w1t);
    cudaGetSymbolAddress((void**)&w2t, g_w2t);
    cudaGetSymbolAddress((void**)&w3t, g_w3t);

    int nb1 = (n + 1023) / 1024;
    int nrb = (n + 127) / 128;

    // 1: preconvert + init counts
    k_pre<<<512, 256>>>(x, W1, W2, W3, in_sizes[0], in_sizes[2], in_sizes[6],
                        in_sizes[10], n);
    // 2: edge histogram
    k_count<<<(e + 255) / 256, 256>>>(ei, e);
    // 3: block-local scan
    k_scan1<<<nb1, 1024>>>(n);
    // 4: layer-1 GEMM (capture slot)
    k_gemm_tc<<<dim3(2, nrb), 256>>>(xt, w1t, bufA, as1, ad1, n, 256, 256);
    // 5: scan finalize (+wptr)
    k_scan3m<<<nb1, 1024>>>(n);
    // 6: scatter edges to CSR
    k_scatter<<<(e + n + 255) / 256, 256>>>(ei, e, n);
    // 7: layer-1 aggregate (+ELU, tf32 out)
    k_agg<<<n, 256>>>(bufA, b1, nullptr, bufBt, 4, 1);
    // 8: layer-2 GEMM
    k_gemm_tc<<<dim3(2, nrb), 256>>>(bufBt, w2t, bufA, as2, ad2, n, 256, 256);
    // 9: layer-2 aggregate
    k_agg<<<n, 256>>>(bufA, b2, nullptr, bufBt, 4, 1);
    // 10: layer-3 GEMM (M=64)
    k_gemm_tc<<<dim3(1, nrb), 256>>>(bufBt, w3t, bufA, as3, ad3, n, 256, 64);
    // 11: layer-3 aggregate -> output (fp32, no ELU)
    k_agg<<<n, 64>>>(bufA, b3, out, nullptr, 1, 0);
}

// round 4
// speedup vs baseline: 1.6926x; 1.1953x over previous
#include <cuda_runtime.h>
#include <cuda_bf16.h>
#include <math.h>
#include <stdint.h>

// ---------------- static scratch (no allocation allowed) ----------------
#define N_CAP 65536
#define E_CAP (1 << 20)

__device__ float    g_bufA[(size_t)N_CAP * 256];   // fp32 h of current layer
__device__ uint32_t g_bufBt[(size_t)N_CAP * 256];  // tf32 agg output
__device__ uint32_t g_xt[(size_t)N_CAP * 256];     // tf32 input x
__device__ uint32_t g_w1t[65536];
__device__ uint32_t g_w2t[65536];
__device__ uint32_t g_w3t[16384];
__device__ float g_als[N_CAP * 4];
__device__ float g_ald[N_CAP * 4];
__device__ int   g_rowptr[N_CAP + 1];
__device__ int   g_wptr[N_CAP];
__device__ int   g_srcs[E_CAP];
__device__ int   g_bsum[80];

__device__ __forceinline__ uint32_t f2tf(float f) {
    uint32_t r;
    asm("cvt.rna.tf32.f32 %0, %1;" : "=r"(r) : "f"(f));
    return r;
}

// ---------------- preconvert + init ----------------
__global__ void k_pre(const float* __restrict__ x, const float* __restrict__ W1,
                      const float* __restrict__ W2, const float* __restrict__ W3,
                      int nx, int nw1, int nw2, int nw3, int n) {
    int i = blockIdx.x * blockDim.x + threadIdx.x;
    int stride = gridDim.x * blockDim.x;
    for (int j = i; j < nx; j += stride) g_xt[j] = f2tf(x[j]);
    for (int j = i; j < nw1; j += stride) g_w1t[j] = f2tf(W1[j]);
    for (int j = i; j < nw2; j += stride) g_w2t[j] = f2tf(W2[j]);
    for (int j = i; j < nw3; j += stride) g_w3t[j] = f2tf(W3[j]);
    for (int j = i; j < n; j += stride) g_wptr[j] = 1;  // self-loop pre-count
}

// ---------------- CSR build ----------------
__global__ void k_count(const int* __restrict__ ei, int e) {
    int t = blockIdx.x * blockDim.x + threadIdx.x;
    if (t < e) atomicAdd(&g_wptr[ei[e + t]], 1);
}

__global__ void k_scan1(int n) {
    __shared__ int sm[1024];
    int t = threadIdx.x;
    int i = blockIdx.x * 1024 + t;
    int v = (i < n) ? g_wptr[i] : 0;
    sm[t] = v;
    __syncthreads();
    for (int off = 1; off < 1024; off <<= 1) {
        int x = (t >= off) ? sm[t - off] : 0;
        __syncthreads();
        sm[t] += x;
        __syncthreads();
    }
    if (i < n) g_rowptr[i + 1] = sm[t];
    if (t == 1023) g_bsum[blockIdx.x] = sm[1023];
}

// merged: cross-block offsets + add + write wptr(=rowptr) for scatter
__global__ void k_scan3m(int n) {
    __shared__ int s_off;
    int t = threadIdx.x, b = blockIdx.x;
    if (t < 32) {
        int acc = 0;
        for (int i = t; i < b; i += 32) acc += g_bsum[i];
#pragma unroll
        for (int o = 16; o; o >>= 1) acc += __shfl_down_sync(0xffffffffu, acc, o);
        if (t == 0) s_off = acc;
    }
    __syncthreads();
    int i = b * 1024 + t;
    if (i < n) {
        int v = g_rowptr[i + 1] + s_off;
        g_rowptr[i + 1] = v;
        if (i + 1 < n) g_wptr[i + 1] = v;
    }
    if (i == 0) { g_rowptr[0] = 0; g_wptr[0] = 0; }
}

__global__ void k_scatter(const int* __restrict__ ei, int e, int n) {
    int t = blockIdx.x * blockDim.x + threadIdx.x;
    if (t < e) {
        int src = ei[t];
        int dst = ei[e + t];
        int pos = atomicAdd(&g_wptr[dst], 1);
        g_srcs[pos] = src;
    } else if (t < e + n) {
        int i = t - e;
        int pos = atomicAdd(&g_wptr[i], 1);
        g_srcs[pos] = i;  // self loop
    }
}

// ---------------- cp.async helpers ----------------
__device__ __forceinline__ void cp16(uint32_t dst, const void* src, int bytes) {
    asm volatile("cp.async.cg.shared.global [%0], [%1], 16, %2;"
                 :: "r"(dst), "l"(src), "r"(bytes));
}
__device__ __forceinline__ void cp_commit() { asm volatile("cp.async.commit_group;"); }
template <int NN> __device__ __forceinline__ void cp_wait() {
    asm volatile("cp.async.wait_group %0;" :: "n"(NN));
}

// ---------------- tf32 tensor-core GEMM + fused attention logits ----------------
// C[n,M] = A[n,K] @ B[K,M], tf32 inputs. Tile 128x128, BK=16, 4-stage cp.async.
// 8 warps = 4 (rows of 32) x 2 (cols of 64 = one head).
#define GEMM_SMEM_BYTES ((4 * 128 * 20 + 4 * 16 * 136 + 768) * 4)
#define AS_IDX(buf, row, col) ((((buf) * 128 + (row)) * 20) + (col))
#define BS_IDX(buf, row, col) ((((buf) * 16 + (row)) * 136) + (col))

__global__ __launch_bounds__(256) void k_gemm_tc(const uint32_t* __restrict__ A,
                                                 const uint32_t* __restrict__ B,
                                                 float* __restrict__ C,
                                                 const float* __restrict__ a_s,
                                                 const float* __restrict__ a_d,
                                                 int n, int K, int M) {
    extern __shared__ uint32_t dynsmem[];
    uint32_t* As = dynsmem;                      // 4*128*20
    uint32_t* Bs = dynsmem + 4 * 128 * 20;       // 4*16*136
    float* s_als = (float*)(Bs + 4 * 16 * 136);  // 128*2
    float* s_ald = s_als + 256;                  // 128*2
    float* s_as  = s_ald + 256;                  // 128
    float* s_ad  = s_as + 128;                   // 128

    int tid = threadIdx.x, lane = tid & 31, warp = tid >> 5;
    int wm = warp >> 1, wn = warp & 1;
    int r0 = blockIdx.y * 128, c0 = blockIdx.x * 128;

    uint32_t as_base = (uint32_t)__cvta_generic_to_shared(As);
    uint32_t bs_base = (uint32_t)__cvta_generic_to_shared(Bs);

    if (tid < 128 && c0 + tid < M) {
        s_as[tid] = a_s[c0 + tid];
        s_ad[tid] = a_d[c0 + tid];
    }

    float acc[2][8][4];
#pragma unroll
    for (int mt = 0; mt < 2; mt++)
#pragma unroll
        for (int nt = 0; nt < 8; nt++)
#pragma unroll
            for (int i = 0; i < 4; i++) acc[mt][nt][i] = 0.f;

    int KT = K >> 4;

#define LOAD_TILE(KT_IDX, BUF)                                                      \
    {                                                                               \
        int k0 = (KT_IDX) << 4;                                                     \
        _Pragma("unroll")                                                           \
        for (int i = 0; i < 2; i++) {                                               \
            int row = (tid >> 2) + 64 * i;                                          \
            int ac = (tid & 3) * 4;                                                 \
            int gr = r0 + row;                                                      \
            const uint32_t* src = A + (size_t)(gr < n ? gr : 0) * K + k0 + ac;      \
            cp16(as_base + AS_IDX(BUF, row, ac) * 4, src, gr < n ? 16 : 0);         \
        }                                                                           \
        _Pragma("unroll")                                                           \
        for (int i = 0; i < 2; i++) {                                               \
            int rr = tid >> 4;                                                      \
            int bc = (tid & 15) * 8 + i * 4;                                        \
            int gc = c0 + bc;                                                       \
            const uint32_t* src = B + (size_t)(k0 + rr) * M + (gc < M ? gc : 0);    \
            cp16(bs_base + BS_IDX(BUF, rr, bc) * 4, src, gc < M ? 16 : 0);          \
        }                                                                           \
    }

    LOAD_TILE(0, 0); cp_commit();
    if (KT > 1) { LOAD_TILE(1, 1); cp_commit(); }
    if (KT > 2) { LOAD_TILE(2, 2); cp_commit(); }

    for (int kt = 0; kt < KT; kt++) {
        if (kt < KT - 2) cp_wait<2>();
        else if (kt == KT - 2) cp_wait<1>();
        else cp_wait<0>();
        __syncthreads();

        int nk = kt + 3;
        if (nk < KT) { LOAD_TILE(nk, nk & 3); cp_commit(); }

        int buf = kt & 3;
#pragma unroll
        for (int ks = 0; ks < 2; ks++) {
            int kb = ks * 8;
            uint32_t a[2][4], b[8][2];
#pragma unroll
            for (int mt = 0; mt < 2; mt++) {
                int row = wm * 32 + mt * 16 + (lane >> 2);
                int col = kb + (lane & 3);
                a[mt][0] = As[AS_IDX(buf, row, col)];
                a[mt][1] = As[AS_IDX(buf, row + 8, col)];
                a[mt][2] = As[AS_IDX(buf, row, col + 4)];
                a[mt][3] = As[AS_IDX(buf, row + 8, col + 4)];
            }
#pragma unroll
            for (int nt = 0; nt < 8; nt++) {
                int nn = wn * 64 + nt * 8 + (lane >> 2);
                int kk = kb + (lane & 3);
                b[nt][0] = Bs[BS_IDX(buf, kk, nn)];
                b[nt][1] = Bs[BS_IDX(buf, kk + 4, nn)];
            }
#pragma unroll
            for (int mt = 0; mt < 2; mt++)
#pragma unroll
                for (int nt = 0; nt < 8; nt++) {
                    asm volatile(
                        "mma.sync.aligned.m16n8k8.row.col.f32.tf32.tf32.f32 "
                        "{%0,%1,%2,%3}, {%4,%5,%6,%7}, {%8,%9}, {%0,%1,%2,%3};"
                        : "+f"(acc[mt][nt][0]), "+f"(acc[mt][nt][1]),
                          "+f"(acc[mt][nt][2]), "+f"(acc[mt][nt][3])
                        : "r"(a[mt][0]), "r"(a[mt][1]), "r"(a[mt][2]), "r"(a[mt][3]),
                          "r"(b[nt][0]), "r"(b[nt][1]));
                }
        }
    }

    // ---- fused attention-logit epilogue + C store ----
    bool colok = (c0 + wn * 64) < M;
    if (colok) {
#pragma unroll
        for (int mt = 0; mt < 2; mt++) {
#pragma unroll
            for (int rr = 0; rr < 2; rr++) {
                float ps = 0.f, pd = 0.f;
#pragma unroll
                for (int nt = 0; nt < 8; nt++)
#pragma unroll
                    for (int q = 0; q < 2; q++) {
                        int lc = nt * 8 + (lane & 3) * 2 + q;
                        float v = acc[mt][nt][rr * 2 + q];
                        ps = fmaf(v, s_as[wn * 64 + lc], ps);
                        pd = fmaf(v, s_ad[wn * 64 + lc], pd);
                    }
                ps += __shfl_down_sync(0xffffffffu, ps, 1);
                ps += __shfl_down_sync(0xffffffffu, ps, 2);
                pd += __shfl_down_sync(0xffffffffu, pd, 1);
                pd += __shfl_down_sync(0xffffffffu, pd, 2);
                if ((lane & 3) == 0) {
                    int rl = wm * 32 + mt * 16 + (lane >> 2) + rr * 8;
                    s_als[rl * 2 + wn] = ps;
                    s_ald[rl * 2 + wn] = pd;
                }
            }
        }
#pragma unroll
        for (int mt = 0; mt < 2; mt++) {
            int row = r0 + wm * 32 + mt * 16 + (lane >> 2);
#pragma unroll
            for (int nt = 0; nt < 8; nt++) {
                int col = c0 + wn * 64 + nt * 8 + (lane & 3) * 2;
                if (row < n)
                    *(float2*)&C[(size_t)row * M + col] =
                        make_float2(acc[mt][nt][0], acc[mt][nt][1]);
                if (row + 8 < n)
                    *(float2*)&C[(size_t)(row + 8) * M + col] =
                        make_float2(acc[mt][nt][2], acc[mt][nt][3]);
            }
        }
    }
    __syncthreads();

    if (tid < 128) {
        int row = r0 + tid;
        if (row < n) {
            int hb = c0 >> 6;
            g_als[row * 4 + hb] = s_als[tid * 2 + 0];
            g_ald[row * 4 + hb] = s_ald[tid * 2 + 0];
            if (c0 + 64 < M) {
                g_als[row * 4 + hb + 1] = s_als[tid * 2 + 1];
                g_ald[row * 4 + hb + 1] = s_ald[tid * 2 + 1];
            }
        }
    }
}

// ---------------- aggregation: one WARP per dst node, no block syncs ----------------
// F channels, H heads. Each lane owns FPL=F/32 contiguous channels (within one head).
template <int F, int H>
__global__ __launch_bounds__(256) void k_agg_w(const float* __restrict__ h,
                                               const float* __restrict__ bias,
                                               float* __restrict__ out,
                                               uint32_t* __restrict__ out_t,
                                               int n, int apply_elu) {
    int gw = (blockIdx.x * 256 + threadIdx.x) >> 5;
    int lane = threadIdx.x & 31;
    if (gw >= n) return;
    constexpr int FPL = F / 32;       // 8 or 2
    constexpr int CH = F / H;         // channels per head (64)
    int hh = (lane * FPL) / CH;       // this lane's head

    int r0 = g_rowptr[gw];
    int deg = g_rowptr[gw + 1] - r0;

    float4 aldv = *(const float4*)&g_ald[gw * 4];
    float ald[4] = {aldv.x, aldv.y, aldv.z, aldv.w};

    // ---- online softmax stats (lane-parallel over edges) ----
    float m[H], sa[H];
#pragma unroll
    for (int i = 0; i < H; i++) { m[i] = -1e30f; sa[i] = 0.f; }
    for (int j = lane; j < deg; j += 32) {
        int src = g_srcs[r0 + j];
        float4 alv = *(const float4*)&g_als[src * 4];
        float al[4] = {alv.x, alv.y, alv.z, alv.w};
#pragma unroll
        for (int i = 0; i < H; i++) {
            float l = al[i] + ald[i];
            l = (l < 0.f) ? 0.2f * l : l;
            float nm = fmaxf(m[i], l);
            sa[i] = sa[i] * __expf(m[i] - nm) + __expf(l - nm);
            m[i] = nm;
        }
    }
#pragma unroll
    for (int o = 16; o; o >>= 1) {
#pragma unroll
        for (int i = 0; i < H; i++) {
            float mo = __shfl_xor_sync(0xffffffffu, m[i], o);
            float so = __shfl_xor_sync(0xffffffffu, sa[i], o);
            float nm = fmaxf(m[i], mo);
            sa[i] = sa[i] * __expf(m[i] - nm) + so * __expf(mo - nm);
            m[i] = nm;
        }
    }
    float mh = m[hh];
    float invh = 1.f / (sa[hh] + 1e-16f);
    float aldh = ald[hh];

    // ---- weighted feature gather ----
    float acc[FPL];
#pragma unroll
    for (int i = 0; i < FPL; i++) acc[i] = 0.f;

    for (int base = 0; base < deg; base += 32) {
        int cnt = min(32, deg - base);
        int mysrc = (base + lane < deg) ? g_srcs[r0 + base + lane] : 0;
        for (int jj = 0; jj < cnt; jj++) {
            int src = __shfl_sync(0xffffffffu, mysrc, jj);
            float l = g_als[src * 4 + hh] + aldh;
            l = (l < 0.f) ? 0.2f * l : l;
            float alpha = __expf(l - mh) * invh;
            const float* hp = &h[(size_t)src * F + lane * FPL];
            if (FPL == 8) {
                float4 v0 = *(const float4*)hp;
                float4 v1 = *(const float4*)(hp + 4);
                acc[0] = fmaf(alpha, v0.x, acc[0]);
                acc[1] = fmaf(alpha, v0.y, acc[1]);
                acc[2] = fmaf(alpha, v0.z, acc[2]);
                acc[3] = fmaf(alpha, v0.w, acc[3]);
                acc[4] = fmaf(alpha, v1.x, acc[4]);
                acc[5] = fmaf(alpha, v1.y, acc[5]);
                acc[6] = fmaf(alpha, v1.z, acc[6]);
                acc[7] = fmaf(alpha, v1.w, acc[7]);
            } else {
                float2 v0 = *(const float2*)hp;
                acc[0] = fmaf(alpha, v0.x, acc[0]);
                acc[1] = fmaf(alpha, v0.y, acc[1]);
            }
        }
    }

    // ---- bias + ELU + store ----
    size_t ob = (size_t)gw * F + lane * FPL;
#pragma unroll
    for (int i = 0; i < FPL; i++) {
        float v = acc[i] + bias[lane * FPL + i];
        if (apply_elu) v = (v > 0.f) ? v : expm1f(v);
        if (out_t) out_t[ob + i] = f2tf(v);
        else out[ob + i] = v;
    }
}

// ---------------- launcher ----------------
extern "C" void kernel_launch(void* const* d_in, const int* in_sizes, int n_in,
                              void* d_out, int out_size) {
    const float* x   = (const float*)d_in[0];
    const int*   ei  = (const int*)d_in[1];
    const float* W1  = (const float*)d_in[2];
    const float* as1 = (const float*)d_in[3];
    const float* ad1 = (const float*)d_in[4];
    const float* b1  = (const float*)d_in[5];
    const float* W2  = (const float*)d_in[6];
    const float* as2 = (const float*)d_in[7];
    const float* ad2 = (const float*)d_in[8];
    const float* b2  = (const float*)d_in[9];
    const float* W3  = (const float*)d_in[10];
    const float* as3 = (const float*)d_in[11];
    const float* ad3 = (const float*)d_in[12];
    const float* b3  = (const float*)d_in[13];
    float* out = (float*)d_out;

    int n = in_sizes[0] / 256;   // 50000
    int e = in_sizes[1] / 2;     // 320000

    float *bufA;
    uint32_t *bufBt, *xt, *w1t, *w2t, *w3t;
    cudaGetSymbolAddress((void**)&bufA, g_bufA);
    cudaGetSymbolAddress((void**)&bufBt, g_bufBt);
    cudaGetSymbolAddress((void**)&xt, g_xt);
    cudaGetSymbolAddress((void**)&w1t, g_w1t);
    cudaGetSymbolAddress((void**)&w2t, g_w2t);
    cudaGetSymbolAddress((void**)&w3t, g_w3t);

    cudaFuncSetAttribute(k_gemm_tc, cudaFuncAttributeMaxDynamicSharedMemorySize,
                         GEMM_SMEM_BYTES);

    int nb1 = (n + 1023) / 1024;
    int nrb = (n + 127) / 128;
    int nab = (n + 7) / 8;   // warp-per-dst agg blocks

    // 1: preconvert + init counts
    k_pre<<<512, 256>>>(x, W1, W2, W3, in_sizes[0], in_sizes[2], in_sizes[6],
                        in_sizes[10], n);
    // 2: edge histogram
    k_count<<<(e + 255) / 256, 256>>>(ei, e);
    // 3: block-local scan
    k_scan1<<<nb1, 1024>>>(n);
    // 4: layer-1 GEMM (capture slot)
    k_gemm_tc<<<dim3(2, nrb), 256, GEMM_SMEM_BYTES>>>(xt, w1t, bufA, as1, ad1, n, 256, 256);
    // 5: scan finalize (+wptr)
    k_scan3m<<<nb1, 1024>>>(n);
    // 6: scatter edges to CSR
    k_scatter<<<(e + n + 255) / 256, 256>>>(ei, e, n);
    // 7: layer-1 aggregate (+ELU, tf32 out)
    k_agg_w<256, 4><<<nab, 256>>>(bufA, b1, nullptr, bufBt, n, 1);
    // 8: layer-2 GEMM
    k_gemm_tc<<<dim3(2, nrb), 256, GEMM_SMEM_BYTES>>>(bufBt, w2t, bufA, as2, ad2, n, 256, 256);
    // 9: layer-2 aggregate
    k_agg_w<256, 4><<<nab, 256>>>(bufA, b2, nullptr, bufBt, n, 1);
    // 10: layer-3 GEMM (M=64)
    k_gemm_tc<<<dim3(1, nrb), 256, GEMM_SMEM_BYTES>>>(bufBt, w3t, bufA, as3, ad3, n, 256, 64);
    // 11: layer-3 aggregate -> output (fp32, no ELU)
    k_agg_w<64, 1><<<nab, 256>>>(bufA, b3, out, nullptr, n, 0);
}

// round 5
// speedup vs baseline: 2.7529x; 1.6264x over previous
#include <cuda_runtime.h>
#include <cuda_bf16.h>
#include <math.h>
#include <stdint.h>

// ---------------- static scratch (no allocation allowed) ----------------
#define N_CAP 65536
#define E_CAP (1 << 20)

__device__ float    g_bufA[(size_t)N_CAP * 256];   // fp32 h of current layer
__device__ uint32_t g_bufBt[(size_t)N_CAP * 256];  // tf32 agg output
__device__ uint32_t g_xt[(size_t)N_CAP * 256];     // tf32 input x
__device__ uint32_t g_w1t[65536];
__device__ uint32_t g_w2t[65536];
__device__ uint32_t g_w3t[16384];
__device__ float g_als[N_CAP * 4];
__device__ float g_ald[N_CAP * 4];
__device__ int   g_rowptr[N_CAP + 1];
__device__ int   g_wptr[N_CAP];
__device__ int   g_srcs[E_CAP];
__device__ int   g_bsum[80];

__device__ __forceinline__ uint32_t f2tf(float f) {
    uint32_t r;
    asm("cvt.rna.tf32.f32 %0, %1;" : "=r"(r) : "f"(f));
    return r;
}

// ---------------- preconvert (vectorized) ----------------
__global__ void k_pre(const float* __restrict__ x, const float* __restrict__ W1,
                      const float* __restrict__ W2, const float* __restrict__ W3,
                      int nx4, int nw1, int nw2, int nw3) {
    int i = blockIdx.x * blockDim.x + threadIdx.x;
    int stride = gridDim.x * blockDim.x;
    const float4* x4 = (const float4*)x;
    uint4* xt4 = (uint4*)g_xt;
    for (int j = i; j < nx4; j += stride) {
        float4 v = x4[j];
        uint4 o;
        o.x = f2tf(v.x); o.y = f2tf(v.y); o.z = f2tf(v.z); o.w = f2tf(v.w);
        xt4[j] = o;
    }
    for (int j = i; j < nw1; j += stride) g_w1t[j] = f2tf(W1[j]);
    for (int j = i; j < nw2; j += stride) g_w2t[j] = f2tf(W2[j]);
    for (int j = i; j < nw3; j += stride) g_w3t[j] = f2tf(W3[j]);
}

// ---------------- CSR build ----------------
__global__ void k_init(int n) {
    int i = blockIdx.x * blockDim.x + threadIdx.x;
    if (i < n) g_wptr[i] = 1;  // self-loop pre-count
}

__global__ void k_count(const int* __restrict__ ei, int e) {
    int t = blockIdx.x * blockDim.x + threadIdx.x;
    if (t < e) atomicAdd(&g_wptr[ei[e + t]], 1);
}

__global__ void k_scan1(int n) {
    __shared__ int sm[1024];
    int t = threadIdx.x;
    int i = blockIdx.x * 1024 + t;
    int v = (i < n) ? g_wptr[i] : 0;
    sm[t] = v;
    __syncthreads();
    for (int off = 1; off < 1024; off <<= 1) {
        int x = (t >= off) ? sm[t - off] : 0;
        __syncthreads();
        sm[t] += x;
        __syncthreads();
    }
    if (i < n) g_rowptr[i + 1] = sm[t];
    if (t == 1023) g_bsum[blockIdx.x] = sm[1023];
}

__global__ void k_scan3m(int n) {
    __shared__ int s_off;
    int t = threadIdx.x, b = blockIdx.x;
    if (t < 32) {
        int acc = 0;
        for (int i = t; i < b; i += 32) acc += g_bsum[i];
#pragma unroll
        for (int o = 16; o; o >>= 1) acc += __shfl_down_sync(0xffffffffu, acc, o);
        if (t == 0) s_off = acc;
    }
    __syncthreads();
    int i = b * 1024 + t;
    if (i < n) {
        int v = g_rowptr[i + 1] + s_off;
        g_rowptr[i + 1] = v;
        if (i + 1 < n) g_wptr[i + 1] = v;
    }
    if (i == 0) { g_rowptr[0] = 0; g_wptr[0] = 0; }
}

__global__ void k_scatter(const int* __restrict__ ei, int e, int n) {
    int t = blockIdx.x * blockDim.x + threadIdx.x;
    if (t < e) {
        int src = ei[t];
        int dst = ei[e + t];
        int pos = atomicAdd(&g_wptr[dst], 1);
        g_srcs[pos] = src;
    } else if (t < e + n) {
        int i = t - e;
        int pos = atomicAdd(&g_wptr[i], 1);
        g_srcs[pos] = i;  // self loop
    }
}

// ---------------- cp.async helpers ----------------
__device__ __forceinline__ void cp16(uint32_t dst, const void* src, int bytes) {
    asm volatile("cp.async.cg.shared.global [%0], [%1], 16, %2;"
                 :: "r"(dst), "l"(src), "r"(bytes));
}
__device__ __forceinline__ void cp_commit() { asm volatile("cp.async.commit_group;"); }
template <int NN> __device__ __forceinline__ void cp_wait() {
    asm volatile("cp.async.wait_group %0;" :: "n"(NN));
}

// ---------------- tf32 tensor-core GEMM + fused attention logits ----------------
// C[n,M] = A[n,K] @ B[K,M], tf32 inputs. Tile 128x128, BK=16, 2-stage cp.async.
// 8 warps = 4 (rows of 32) x 2 (cols of 64 = one head).
__global__ __launch_bounds__(256) void k_gemm_tc(const uint32_t* __restrict__ A,
                                                 const uint32_t* __restrict__ B,
                                                 float* __restrict__ C,
                                                 const float* __restrict__ a_s,
                                                 const float* __restrict__ a_d,
                                                 int n, int K, int M) {
    __shared__ uint32_t As[2][128][20];   // 16 cols used, pad 4
    __shared__ uint32_t Bs[2][16][136];   // 128 cols used, pad 8
    __shared__ float s_als[128][2], s_ald[128][2];
    __shared__ float s_as[128], s_ad[128];

    int tid = threadIdx.x, lane = tid & 31, warp = tid >> 5;
    int wm = warp >> 1, wn = warp & 1;
    int r0 = blockIdx.y * 128, c0 = blockIdx.x * 128;

    uint32_t as_base = (uint32_t)__cvta_generic_to_shared(&As[0][0][0]);
    uint32_t bs_base = (uint32_t)__cvta_generic_to_shared(&Bs[0][0][0]);

    if (tid < 128 && c0 + tid < M) {
        s_as[tid] = a_s[c0 + tid];
        s_ad[tid] = a_d[c0 + tid];
    }

    float acc[2][8][4];
#pragma unroll
    for (int mt = 0; mt < 2; mt++)
#pragma unroll
        for (int nt = 0; nt < 8; nt++)
#pragma unroll
            for (int i = 0; i < 4; i++) acc[mt][nt][i] = 0.f;

    int KT = K >> 4;

#define LOAD_TILE(KT_IDX, BUF)                                                      \
    {                                                                               \
        int k0 = (KT_IDX) << 4;                                                     \
        _Pragma("unroll")                                                           \
        for (int i = 0; i < 2; i++) {                                               \
            int row = (tid >> 2) + 64 * i;                                          \
            int ac = (tid & 3) * 4;                                                 \
            int gr = r0 + row;                                                      \
            const uint32_t* src = A + (size_t)(gr < n ? gr : 0) * K + k0 + ac;      \
            cp16(as_base + (((BUF) * 128 + row) * 20 + ac) * 4, src,                \
                 gr < n ? 16 : 0);                                                  \
        }                                                                           \
        _Pragma("unroll")                                                           \
        for (int i = 0; i < 2; i++) {                                               \
            int rr = tid >> 4;                                                      \
            int bc = (tid & 15) * 8 + i * 4;                                        \
            int gc = c0 + bc;                                                       \
            const uint32_t* src = B + (size_t)(k0 + rr) * M + (gc < M ? gc : 0);    \
            cp16(bs_base + (((BUF) * 16 + rr) * 136 + bc) * 4, src,                 \
                 gc < M ? 16 : 0);                                                  \
        }                                                                           \
    }

    LOAD_TILE(0, 0);
    cp_commit();

    for (int kt = 0; kt < KT; kt++) {
        int buf = kt & 1;
        if (kt + 1 < KT) {
            LOAD_TILE(kt + 1, buf ^ 1);
            cp_commit();
            cp_wait<1>();
        } else {
            cp_wait<0>();
        }
        __syncthreads();

#pragma unroll
        for (int ks = 0; ks < 2; ks++) {
            int kb = ks * 8;
            uint32_t a[2][4], b[8][2];
#pragma unroll
            for (int mt = 0; mt < 2; mt++) {
                int row = wm * 32 + mt * 16 + (lane >> 2);
                int col = kb + (lane & 3);
                a[mt][0] = As[buf][row][col];
                a[mt][1] = As[buf][row + 8][col];
                a[mt][2] = As[buf][row][col + 4];
                a[mt][3] = As[buf][row + 8][col + 4];
            }
#pragma unroll
            for (int nt = 0; nt < 8; nt++) {
                int nn = wn * 64 + nt * 8 + (lane >> 2);
                int kk = kb + (lane & 3);
                b[nt][0] = Bs[buf][kk][nn];
                b[nt][1] = Bs[buf][kk + 4][nn];
            }
#pragma unroll
            for (int mt = 0; mt < 2; mt++)
#pragma unroll
                for (int nt = 0; nt < 8; nt++) {
                    asm volatile(
                        "mma.sync.aligned.m16n8k8.row.col.f32.tf32.tf32.f32 "
                        "{%0,%1,%2,%3}, {%4,%5,%6,%7}, {%8,%9}, {%0,%1,%2,%3};"
                        : "+f"(acc[mt][nt][0]), "+f"(acc[mt][nt][1]),
                          "+f"(acc[mt][nt][2]), "+f"(acc[mt][nt][3])
                        : "r"(a[mt][0]), "r"(a[mt][1]), "r"(a[mt][2]), "r"(a[mt][3]),
                          "r"(b[nt][0]), "r"(b[nt][1]));
                }
        }
        __syncthreads();
    }

    // ---- fused attention-logit epilogue + C store ----
    bool colok = (c0 + wn * 64) < M;
    if (colok) {
#pragma unroll
        for (int mt = 0; mt < 2; mt++) {
#pragma unroll
            for (int rr = 0; rr < 2; rr++) {
                float ps = 0.f, pd = 0.f;
#pragma unroll
                for (int nt = 0; nt < 8; nt++)
#pragma unroll
                    for (int q = 0; q < 2; q++) {
                        int lc = nt * 8 + (lane & 3) * 2 + q;
                        float v = acc[mt][nt][rr * 2 + q];
                        ps = fmaf(v, s_as[wn * 64 + lc], ps);
                        pd = fmaf(v, s_ad[wn * 64 + lc], pd);
                    }
                ps += __shfl_down_sync(0xffffffffu, ps, 1);
                ps += __shfl_down_sync(0xffffffffu, ps, 2);
                pd += __shfl_down_sync(0xffffffffu, pd, 1);
                pd += __shfl_down_sync(0xffffffffu, pd, 2);
                if ((lane & 3) == 0) {
                    int rl = wm * 32 + mt * 16 + (lane >> 2) + rr * 8;
                    s_als[rl][wn] = ps;
                    s_ald[rl][wn] = pd;
                }
            }
        }
#pragma unroll
        for (int mt = 0; mt < 2; mt++) {
            int row = r0 + wm * 32 + mt * 16 + (lane >> 2);
#pragma unroll
            for (int nt = 0; nt < 8; nt++) {
                int col = c0 + wn * 64 + nt * 8 + (lane & 3) * 2;
                if (row < n)
                    *(float2*)&C[(size_t)row * M + col] =
                        make_float2(acc[mt][nt][0], acc[mt][nt][1]);
                if (row + 8 < n)
                    *(float2*)&C[(size_t)(row + 8) * M + col] =
                        make_float2(acc[mt][nt][2], acc[mt][nt][3]);
            }
        }
    }
    __syncthreads();

    if (tid < 128) {
        int row = r0 + tid;
        if (row < n) {
            int hb = c0 >> 6;
            g_als[row * 4 + hb] = s_als[tid][0];
            g_ald[row * 4 + hb] = s_ald[tid][0];
            if (c0 + 64 < M) {
                g_als[row * 4 + hb + 1] = s_als[tid][1];
                g_ald[row * 4 + hb + 1] = s_ald[tid][1];
            }
        }
    }
}

// ---------------- aggregation: one WARP per dst node, no block syncs ----------------
template <int F, int H>
__global__ __launch_bounds__(256) void k_agg_w(const float* __restrict__ h,
                                               const float* __restrict__ bias,
                                               float* __restrict__ out,
                                               uint32_t* __restrict__ out_t,
                                               int n, int apply_elu) {
    int gw = (blockIdx.x * 256 + threadIdx.x) >> 5;
    int lane = threadIdx.x & 31;
    if (gw >= n) return;
    constexpr int FPL = F / 32;       // 8 or 2
    constexpr int CH = F / H;         // channels per head (64)
    int hh = (lane * FPL) / CH;       // this lane's head

    int r0 = g_rowptr[gw];
    int deg = g_rowptr[gw + 1] - r0;

    float4 aldv = *(const float4*)&g_ald[gw * 4];
    float ald[4] = {aldv.x, aldv.y, aldv.z, aldv.w};

    // ---- online softmax stats (lane-parallel over edges) ----
    float m[H], sa[H];
#pragma unroll
    for (int i = 0; i < H; i++) { m[i] = -1e30f; sa[i] = 0.f; }
    for (int j = lane; j < deg; j += 32) {
        int src = __ldg(&g_srcs[r0 + j]);
        float4 alv = *(const float4*)&g_als[src * 4];
        float al[4] = {alv.x, alv.y, alv.z, alv.w};
#pragma unroll
        for (int i = 0; i < H; i++) {
            float l = al[i] + ald[i];
            l = (l < 0.f) ? 0.2f * l : l;
            float nm = fmaxf(m[i], l);
            sa[i] = sa[i] * __expf(m[i] - nm) + __expf(l - nm);
            m[i] = nm;
        }
    }
#pragma unroll
    for (int o = 16; o; o >>= 1) {
#pragma unroll
        for (int i = 0; i < H; i++) {
            float mo = __shfl_xor_sync(0xffffffffu, m[i], o);
            float so = __shfl_xor_sync(0xffffffffu, sa[i], o);
            float nm = fmaxf(m[i], mo);
            sa[i] = sa[i] * __expf(m[i] - nm) + so * __expf(mo - nm);
            m[i] = nm;
        }
    }
    float mh = m[hh];
    float invh = 1.f / (sa[hh] + 1e-16f);
    float aldh = ald[hh];

    // ---- weighted feature gather (unrolled x2 for MLP) ----
    float acc[FPL];
#pragma unroll
    for (int i = 0; i < FPL; i++) acc[i] = 0.f;

    for (int base = 0; base < deg; base += 32) {
        int cnt = min(32, deg - base);
        int mysrc = (base + lane < deg) ? g_srcs[r0 + base + lane] : 0;
        int jj = 0;
        for (; jj + 2 <= cnt; jj += 2) {
            int s0 = __shfl_sync(0xffffffffu, mysrc, jj);
            int s1 = __shfl_sync(0xffffffffu, mysrc, jj + 1);
            float l0 = g_als[s0 * 4 + hh] + aldh;
            float l1 = g_als[s1 * 4 + hh] + aldh;
            l0 = (l0 < 0.f) ? 0.2f * l0 : l0;
            l1 = (l1 < 0.f) ? 0.2f * l1 : l1;
            float a0 = __expf(l0 - mh) * invh;
            float a1 = __expf(l1 - mh) * invh;
            const float* h0 = &h[(size_t)s0 * F + lane * FPL];
            const float* h1 = &h[(size_t)s1 * F + lane * FPL];
            if (FPL == 8) {
                float4 u0 = *(const float4*)h0;
                float4 u1 = *(const float4*)(h0 + 4);
                float4 w0 = *(const float4*)h1;
                float4 w1 = *(const float4*)(h1 + 4);
                acc[0] = fmaf(a0, u0.x, fmaf(a1, w0.x, acc[0]));
                acc[1] = fmaf(a0, u0.y, fmaf(a1, w0.y, acc[1]));
                acc[2] = fmaf(a0, u0.z, fmaf(a1, w0.z, acc[2]));
                acc[3] = fmaf(a0, u0.w, fmaf(a1, w0.w, acc[3]));
                acc[4] = fmaf(a0, u1.x, fmaf(a1, w1.x, acc[4]));
                acc[5] = fmaf(a0, u1.y, fmaf(a1, w1.y, acc[5]));
                acc[6] = fmaf(a0, u1.z, fmaf(a1, w1.z, acc[6]));
                acc[7] = fmaf(a0, u1.w, fmaf(a1, w1.w, acc[7]));
            } else {
                float2 u = *(const float2*)h0;
                float2 w = *(const float2*)h1;
                acc[0] = fmaf(a0, u.x, fmaf(a1, w.x, acc[0]));
                acc[1] = fmaf(a0, u.y, fmaf(a1, w.y, acc[1]));
            }
        }
        if (jj < cnt) {
            int s0 = __shfl_sync(0xffffffffu, mysrc, jj);
            float l0 = g_als[s0 * 4 + hh] + aldh;
            l0 = (l0 < 0.f) ? 0.2f * l0 : l0;
            float a0 = __expf(l0 - mh) * invh;
            const float* h0 = &h[(size_t)s0 * F + lane * FPL];
            if (FPL == 8) {
                float4 u0 = *(const float4*)h0;
                float4 u1 = *(const float4*)(h0 + 4);
                acc[0] = fmaf(a0, u0.x, acc[0]);
                acc[1] = fmaf(a0, u0.y, acc[1]);
                acc[2] = fmaf(a0, u0.z, acc[2]);
                acc[3] = fmaf(a0, u0.w, acc[3]);
                acc[4] = fmaf(a0, u1.x, acc[4]);
                acc[5] = fmaf(a0, u1.y, acc[5]);
                acc[6] = fmaf(a0, u1.z, acc[6]);
                acc[7] = fmaf(a0, u1.w, acc[7]);
            } else {
                float2 u = *(const float2*)h0;
                acc[0] = fmaf(a0, u.x, acc[0]);
                acc[1] = fmaf(a0, u.y, acc[1]);
            }
        }
    }

    // ---- bias + ELU + store ----
    size_t ob = (size_t)gw * F + lane * FPL;
#pragma unroll
    for (int i = 0; i < FPL; i++) {
        float v = acc[i] + bias[lane * FPL + i];
        if (apply_elu) v = (v > 0.f) ? v : expm1f(v);
        if (out_t) out_t[ob + i] = f2tf(v);
        else out[ob + i] = v;
    }
}

// ---------------- launcher ----------------
extern "C" void kernel_launch(void* const* d_in, const int* in_sizes, int n_in,
                              void* d_out, int out_size) {
    const float* x   = (const float*)d_in[0];
    const int*   ei  = (const int*)d_in[1];
    const float* W1  = (const float*)d_in[2];
    const float* as1 = (const float*)d_in[3];
    const float* ad1 = (const float*)d_in[4];
    const float* b1  = (const float*)d_in[5];
    const float* W2  = (const float*)d_in[6];
    const float* as2 = (const float*)d_in[7];
    const float* ad2 = (const float*)d_in[8];
    const float* b2  = (const float*)d_in[9];
    const float* W3  = (const float*)d_in[10];
    const float* as3 = (const float*)d_in[11];
    const float* ad3 = (const float*)d_in[12];
    const float* b3  = (const float*)d_in[13];
    float* out = (float*)d_out;

    int n = in_sizes[0] / 256;   // 50000
    int e = in_sizes[1] / 2;     // 320000

    float *bufA;
    uint32_t *bufBt, *xt, *w1t, *w2t, *w3t;
    cudaGetSymbolAddress((void**)&bufA, g_bufA);
    cudaGetSymbolAddress((void**)&bufBt, g_bufBt);
    cudaGetSymbolAddress((void**)&xt, g_xt);
    cudaGetSymbolAddress((void**)&w1t, g_w1t);
    cudaGetSymbolAddress((void**)&w2t, g_w2t);
    cudaGetSymbolAddress((void**)&w3t, g_w3t);

    int nb1 = (n + 1023) / 1024;
    int nrb = (n + 127) / 128;
    int nab = (n + 7) / 8;   // warp-per-dst agg blocks

    // side stream for CSR build, overlapped with preconvert + layer-1 GEMM.
    // (streams/events are host/driver objects, not device memory; replays run
    //  the captured graph so per-call creation is not on the timed path)
    cudaStream_t s2;
    cudaStreamCreateWithFlags(&s2, cudaStreamNonBlocking);
    cudaEvent_t ev1, ev2;
    cudaEventCreateWithFlags(&ev1, cudaEventDisableTiming);
    cudaEventCreateWithFlags(&ev2, cudaEventDisableTiming);

    cudaEventRecord(ev1, 0);
    cudaStreamWaitEvent(s2, ev1, 0);

    // default stream: preconvert + layer-1 GEMM
    k_pre<<<512, 256>>>(x, W1, W2, W3, in_sizes[0] / 4, in_sizes[2], in_sizes[6],
                        in_sizes[10]);
    k_gemm_tc<<<dim3(2, nrb), 256>>>(xt, w1t, bufA, as1, ad1, n, 256, 256);

    // side stream: CSR build
    k_init<<<(n + 255) / 256, 256, 0, s2>>>(n);
    k_count<<<(e + 255) / 256, 256, 0, s2>>>(ei, e);
    k_scan1<<<nb1, 1024, 0, s2>>>(n);
    k_scan3m<<<nb1, 1024, 0, s2>>>(n);
    k_scatter<<<(e + n + 255) / 256, 256, 0, s2>>>(ei, e, n);
    cudaEventRecord(ev2, s2);

    // join: aggregation needs both GEMM-1 and CSR
    cudaStreamWaitEvent(0, ev2, 0);

    k_agg_w<256, 4><<<nab, 256>>>(bufA, b1, nullptr, bufBt, n, 1);
    k_gemm_tc<<<dim3(2, nrb), 256>>>(bufBt, w2t, bufA, as2, ad2, n, 256, 256);
    k_agg_w<256, 4><<<nab, 256>>>(bufA, b2, nullptr, bufBt, n, 1);
    k_gemm_tc<<<dim3(1, nrb), 256>>>(bufBt, w3t, bufA, as3, ad3, n, 256, 64);
    k_agg_w<64, 1><<<nab, 256>>>(bufA, b3, out, nullptr, n, 0);
}

// round 6
// speedup vs baseline: 2.7925x; 1.0144x over previous
#include <cuda_runtime.h>
#include <cuda_bf16.h>
#include <math.h>
#include <stdint.h>

// ---------------- static scratch (no allocation allowed) ----------------
#define N_CAP 65536
#define E_CAP (1 << 20)

__device__ float    g_bufA[(size_t)N_CAP * 256];   // fp32 h of current layer
__device__ uint32_t g_bufBt[(size_t)N_CAP * 256];  // tf32 agg output
__device__ uint32_t g_xt[(size_t)N_CAP * 256];     // tf32 input x
__device__ uint32_t g_w1t[65536];
__device__ uint32_t g_w2t[65536];
__device__ uint32_t g_w3t[16384];
__device__ float g_als[N_CAP * 4];
__device__ float g_ald[N_CAP * 4];
__device__ int   g_rowptr[N_CAP + 1];
__device__ int   g_wptr[N_CAP];
__device__ int   g_srcs[E_CAP];
__device__ int   g_bsum[80];

__device__ __forceinline__ uint32_t f2tf(float f) {
    uint32_t r;
    asm("cvt.rna.tf32.f32 %0, %1;" : "=r"(r) : "f"(f));
    return r;
}

// ---------------- preconvert (vectorized) ----------------
__global__ void k_pre(const float* __restrict__ x, const float* __restrict__ W1,
                      const float* __restrict__ W2, const float* __restrict__ W3,
                      int nx4, int nw1, int nw2, int nw3) {
    int i = blockIdx.x * blockDim.x + threadIdx.x;
    int stride = gridDim.x * blockDim.x;
    const float4* x4 = (const float4*)x;
    uint4* xt4 = (uint4*)g_xt;
    for (int j = i; j < nx4; j += stride) {
        float4 v = x4[j];
        uint4 o;
        o.x = f2tf(v.x); o.y = f2tf(v.y); o.z = f2tf(v.z); o.w = f2tf(v.w);
        xt4[j] = o;
    }
    for (int j = i; j < nw1; j += stride) g_w1t[j] = f2tf(W1[j]);
    for (int j = i; j < nw2; j += stride) g_w2t[j] = f2tf(W2[j]);
    for (int j = i; j < nw3; j += stride) g_w3t[j] = f2tf(W3[j]);
}

// ---------------- CSR build ----------------
__global__ void k_init(int n) {
    int i = blockIdx.x * blockDim.x + threadIdx.x;
    if (i < n) g_wptr[i] = 1;  // self-loop pre-count
}

__global__ void k_count(const int* __restrict__ ei, int e) {
    int t = blockIdx.x * blockDim.x + threadIdx.x;
    if (t < e) atomicAdd(&g_wptr[ei[e + t]], 1);
}

__global__ void k_scan1(int n) {
    __shared__ int sm[1024];
    int t = threadIdx.x;
    int i = blockIdx.x * 1024 + t;
    int v = (i < n) ? g_wptr[i] : 0;
    sm[t] = v;
    __syncthreads();
    for (int off = 1; off < 1024; off <<= 1) {
        int x = (t >= off) ? sm[t - off] : 0;
        __syncthreads();
        sm[t] += x;
        __syncthreads();
    }
    if (i < n) g_rowptr[i + 1] = sm[t];
    if (t == 1023) g_bsum[blockIdx.x] = sm[1023];
}

__global__ void k_scan3m(int n) {
    __shared__ int s_off;
    int t = threadIdx.x, b = blockIdx.x;
    if (t < 32) {
        int acc = 0;
        for (int i = t; i < b; i += 32) acc += g_bsum[i];
#pragma unroll
        for (int o = 16; o; o >>= 1) acc += __shfl_down_sync(0xffffffffu, acc, o);
        if (t == 0) s_off = acc;
    }
    __syncthreads();
    int i = b * 1024 + t;
    if (i < n) {
        int v = g_rowptr[i + 1] + s_off;
        g_rowptr[i + 1] = v;
        if (i + 1 < n) g_wptr[i + 1] = v;
    }
    if (i == 0) { g_rowptr[0] = 0; g_wptr[0] = 0; }
}

__global__ void k_scatter(const int* __restrict__ ei, int e, int n) {
    int t = blockIdx.x * blockDim.x + threadIdx.x;
    if (t < e) {
        int src = ei[t];
        int dst = ei[e + t];
        int pos = atomicAdd(&g_wptr[dst], 1);
        g_srcs[pos] = src;
    } else if (t < e + n) {
        int i = t - e;
        int pos = atomicAdd(&g_wptr[i], 1);
        g_srcs[pos] = i;  // self loop
    }
}

// ---------------- cp.async helpers ----------------
__device__ __forceinline__ void cp16(uint32_t dst, const void* src, int bytes) {
    asm volatile("cp.async.cg.shared.global [%0], [%1], 16, %2;"
                 :: "r"(dst), "l"(src), "r"(bytes));
}
__device__ __forceinline__ void cp_commit() { asm volatile("cp.async.commit_group;"); }
template <int NN> __device__ __forceinline__ void cp_wait() {
    asm volatile("cp.async.wait_group %0;" :: "n"(NN));
}

// ---------------- tf32 tensor-core GEMM + fused attention logits ----------------
// C[n,M] = A[n,K] @ B[K,M], tf32 inputs. Tile 128x128, BK=16, 2-stage cp.async.
// 4 warps in 2x2; each warp computes a 64x64 tile (high smem reuse: LDS-byte
// traffic per MAC halved vs 32x64 warp tiles -> tensor pipe becomes the bound).
__global__ __launch_bounds__(128) void k_gemm_tc(const uint32_t* __restrict__ A,
                                                 const uint32_t* __restrict__ B,
                                                 float* __restrict__ C,
                                                 const float* __restrict__ a_s,
                                                 const float* __restrict__ a_d,
                                                 int n, int K, int M) {
    __shared__ uint32_t As[2][128][20];   // 16 cols used, pad 4
    __shared__ uint32_t Bs[2][16][136];   // 128 cols used, pad 8
    __shared__ float s_als[128][2], s_ald[128][2];
    __shared__ float s_as[128], s_ad[128];

    int tid = threadIdx.x, lane = tid & 31, warp = tid >> 5;
    int wm = warp >> 1, wn = warp & 1;    // 2 x 2 warp grid, 64x64 each
    int r0 = blockIdx.y * 128, c0 = blockIdx.x * 128;

    uint32_t as_base = (uint32_t)__cvta_generic_to_shared(&As[0][0][0]);
    uint32_t bs_base = (uint32_t)__cvta_generic_to_shared(&Bs[0][0][0]);

    if (c0 + tid < M) {
        s_as[tid] = a_s[c0 + tid];
        s_ad[tid] = a_d[c0 + tid];
    }

    float acc[4][8][4];
#pragma unroll
    for (int mt = 0; mt < 4; mt++)
#pragma unroll
        for (int nt = 0; nt < 8; nt++)
#pragma unroll
            for (int i = 0; i < 4; i++) acc[mt][nt][i] = 0.f;

    int KT = K >> 4;

#define LOAD_TILE(KT_IDX, BUF)                                                      \
    {                                                                               \
        int k0 = (KT_IDX) << 4;                                                     \
        _Pragma("unroll")                                                           \
        for (int i = 0; i < 4; i++) {                                               \
            int row = (tid >> 2) + 32 * i;                                          \
            int ac = (tid & 3) * 4;                                                 \
            int gr = r0 + row;                                                      \
            const uint32_t* src = A + (size_t)(gr < n ? gr : 0) * K + k0 + ac;      \
            cp16(as_base + (((BUF) * 128 + row) * 20 + ac) * 4, src,                \
                 gr < n ? 16 : 0);                                                  \
        }                                                                           \
        _Pragma("unroll")                                                           \
        for (int i = 0; i < 2; i++) {                                               \
            int rr = (tid >> 4) + 8 * i;                                            \
            int bc = (tid & 15) * 8;                                                \
            const uint32_t* srcb = B + (size_t)(k0 + rr) * M;                       \
            int g0 = c0 + bc;                                                       \
            cp16(bs_base + (((BUF) * 16 + rr) * 136 + bc) * 4,                      \
                 srcb + (g0 < M ? g0 : 0), g0 < M ? 16 : 0);                        \
            int g1 = c0 + bc + 4;                                                   \
            cp16(bs_base + (((BUF) * 16 + rr) * 136 + bc + 4) * 4,                  \
                 srcb + (g1 < M ? g1 : 0), g1 < M ? 16 : 0);                        \
        }                                                                           \
    }

    LOAD_TILE(0, 0);
    cp_commit();

    for (int kt = 0; kt < KT; kt++) {
        int buf = kt & 1;
        if (kt + 1 < KT) {
            LOAD_TILE(kt + 1, buf ^ 1);
            cp_commit();
            cp_wait<1>();
        } else {
            cp_wait<0>();
        }
        __syncthreads();

#pragma unroll
        for (int ks = 0; ks < 2; ks++) {
            int kb = ks * 8;
            uint32_t a[4][4], b[8][2];
#pragma unroll
            for (int mt = 0; mt < 4; mt++) {
                int row = wm * 64 + mt * 16 + (lane >> 2);
                int col = kb + (lane & 3);
                a[mt][0] = As[buf][row][col];
                a[mt][1] = As[buf][row + 8][col];
                a[mt][2] = As[buf][row][col + 4];
                a[mt][3] = As[buf][row + 8][col + 4];
            }
#pragma unroll
            for (int nt = 0; nt < 8; nt++) {
                int nn = wn * 64 + nt * 8 + (lane >> 2);
                int kk = kb + (lane & 3);
                b[nt][0] = Bs[buf][kk][nn];
                b[nt][1] = Bs[buf][kk + 4][nn];
            }
#pragma unroll
            for (int mt = 0; mt < 4; mt++)
#pragma unroll
                for (int nt = 0; nt < 8; nt++) {
                    asm volatile(
                        "mma.sync.aligned.m16n8k8.row.col.f32.tf32.tf32.f32 "
                        "{%0,%1,%2,%3}, {%4,%5,%6,%7}, {%8,%9}, {%0,%1,%2,%3};"
                        : "+f"(acc[mt][nt][0]), "+f"(acc[mt][nt][1]),
                          "+f"(acc[mt][nt][2]), "+f"(acc[mt][nt][3])
                        : "r"(a[mt][0]), "r"(a[mt][1]), "r"(a[mt][2]), "r"(a[mt][3]),
                          "r"(b[nt][0]), "r"(b[nt][1]));
                }
        }
        __syncthreads();
    }

    // ---- fused attention-logit epilogue + C store ----
    bool colok = (c0 + wn * 64) < M;
    if (colok) {
#pragma unroll
        for (int mt = 0; mt < 4; mt++) {
#pragma unroll
            for (int rr = 0; rr < 2; rr++) {
                float ps = 0.f, pd = 0.f;
#pragma unroll
                for (int nt = 0; nt < 8; nt++)
#pragma unroll
                    for (int q = 0; q < 2; q++) {
                        int lc = nt * 8 + (lane & 3) * 2 + q;
                        float v = acc[mt][nt][rr * 2 + q];
                        ps = fmaf(v, s_as[wn * 64 + lc], ps);
                        pd = fmaf(v, s_ad[wn * 64 + lc], pd);
                    }
                ps += __shfl_down_sync(0xffffffffu, ps, 1);
                ps += __shfl_down_sync(0xffffffffu, ps, 2);
                pd += __shfl_down_sync(0xffffffffu, pd, 1);
                pd += __shfl_down_sync(0xffffffffu, pd, 2);
                if ((lane & 3) == 0) {
                    int rl = wm * 64 + mt * 16 + (lane >> 2) + rr * 8;
                    s_als[rl][wn] = ps;
                    s_ald[rl][wn] = pd;
                }
            }
        }
#pragma unroll
        for (int mt = 0; mt < 4; mt++) {
            int row = r0 + wm * 64 + mt * 16 + (lane >> 2);
#pragma unroll
            for (int nt = 0; nt < 8; nt++) {
                int col = c0 + wn * 64 + nt * 8 + (lane & 3) * 2;
                if (row < n)
                    *(float2*)&C[(size_t)row * M + col] =
                        make_float2(acc[mt][nt][0], acc[mt][nt][1]);
                if (row + 8 < n)
                    *(float2*)&C[(size_t)(row + 8) * M + col] =
                        make_float2(acc[mt][nt][2], acc[mt][nt][3]);
            }
        }
    }
    __syncthreads();

    {
        int row = r0 + tid;
        if (row < n) {
            int hb = c0 >> 6;
            g_als[row * 4 + hb] = s_als[tid][0];
            g_ald[row * 4 + hb] = s_ald[tid][0];
            if (c0 + 64 < M) {
                g_als[row * 4 + hb + 1] = s_als[tid][1];
                g_ald[row * 4 + hb + 1] = s_ald[tid][1];
            }
        }
    }
}

// ---------------- aggregation: one WARP per dst node, no block syncs ----------------
template <int F, int H>
__global__ __launch_bounds__(256) void k_agg_w(const float* __restrict__ h,
                                               const float* __restrict__ bias,
                                               float* __restrict__ out,
                                               uint32_t* __restrict__ out_t,
                                               int n, int apply_elu) {
    int gw = (blockIdx.x * 256 + threadIdx.x) >> 5;
    int lane = threadIdx.x & 31;
    if (gw >= n) return;
    constexpr int FPL = F / 32;       // 8 or 2
    constexpr int CH = F / H;         // channels per head (64)
    int hh = (lane * FPL) / CH;       // this lane's head

    int r0 = g_rowptr[gw];
    int deg = g_rowptr[gw + 1] - r0;

    float4 aldv = *(const float4*)&g_ald[gw * 4];
    float ald[4] = {aldv.x, aldv.y, aldv.z, aldv.w};

    // ---- online softmax stats (lane-parallel over edges) ----
    float m[H], sa[H];
#pragma unroll
    for (int i = 0; i < H; i++) { m[i] = -1e30f; sa[i] = 0.f; }
    for (int j = lane; j < deg; j += 32) {
        int src = __ldg(&g_srcs[r0 + j]);
        float4 alv = *(const float4*)&g_als[src * 4];
        float al[4] = {alv.x, alv.y, alv.z, alv.w};
#pragma unroll
        for (int i = 0; i < H; i++) {
            float l = al[i] + ald[i];
            l = (l < 0.f) ? 0.2f * l : l;
            float nm = fmaxf(m[i], l);
            sa[i] = sa[i] * __expf(m[i] - nm) + __expf(l - nm);
            m[i] = nm;
        }
    }
#pragma unroll
    for (int o = 16; o; o >>= 1) {
#pragma unroll
        for (int i = 0; i < H; i++) {
            float mo = __shfl_xor_sync(0xffffffffu, m[i], o);
            float so = __shfl_xor_sync(0xffffffffu, sa[i], o);
            float nm = fmaxf(m[i], mo);
            sa[i] = sa[i] * __expf(m[i] - nm) + so * __expf(mo - nm);
            m[i] = nm;
        }
    }
    float mh = m[hh];
    float invh = 1.f / (sa[hh] + 1e-16f);
    float aldh = ald[hh];

    // ---- weighted feature gather (unrolled x2 for MLP) ----
    float acc[FPL];
#pragma unroll
    for (int i = 0; i < FPL; i++) acc[i] = 0.f;

    for (int base = 0; base < deg; base += 32) {
        int cnt = min(32, deg - base);
        int mysrc = (base + lane < deg) ? g_srcs[r0 + base + lane] : 0;
        int jj = 0;
        for (; jj + 2 <= cnt; jj += 2) {
            int s0 = __shfl_sync(0xffffffffu, mysrc, jj);
            int s1 = __shfl_sync(0xffffffffu, mysrc, jj + 1);
            float l0 = g_als[s0 * 4 + hh] + aldh;
            float l1 = g_als[s1 * 4 + hh] + aldh;
            l0 = (l0 < 0.f) ? 0.2f * l0 : l0;
            l1 = (l1 < 0.f) ? 0.2f * l1 : l1;
            float a0 = __expf(l0 - mh) * invh;
            float a1 = __expf(l1 - mh) * invh;
            const float* h0 = &h[(size_t)s0 * F + lane * FPL];
            const float* h1 = &h[(size_t)s1 * F + lane * FPL];
            if (FPL == 8) {
                float4 u0 = *(const float4*)h0;
                float4 u1 = *(const float4*)(h0 + 4);
                float4 w0 = *(const float4*)h1;
                float4 w1 = *(const float4*)(h1 + 4);
                acc[0] = fmaf(a0, u0.x, fmaf(a1, w0.x, acc[0]));
                acc[1] = fmaf(a0, u0.y, fmaf(a1, w0.y, acc[1]));
                acc[2] = fmaf(a0, u0.z, fmaf(a1, w0.z, acc[2]));
                acc[3] = fmaf(a0, u0.w, fmaf(a1, w0.w, acc[3]));
                acc[4] = fmaf(a0, u1.x, fmaf(a1, w1.x, acc[4]));
                acc[5] = fmaf(a0, u1.y, fmaf(a1, w1.y, acc[5]));
                acc[6] = fmaf(a0, u1.z, fmaf(a1, w1.z, acc[6]));
                acc[7] = fmaf(a0, u1.w, fmaf(a1, w1.w, acc[7]));
            } else {
                float2 u = *(const float2*)h0;
                float2 w = *(const float2*)h1;
                acc[0] = fmaf(a0, u.x, fmaf(a1, w.x, acc[0]));
                acc[1] = fmaf(a0, u.y, fmaf(a1, w.y, acc[1]));
            }
        }
        if (jj < cnt) {
            int s0 = __shfl_sync(0xffffffffu, mysrc, jj);
            float l0 = g_als[s0 * 4 + hh] + aldh;
            l0 = (l0 < 0.f) ? 0.2f * l0 : l0;
            float a0 = __expf(l0 - mh) * invh;
            const float* h0 = &h[(size_t)s0 * F + lane * FPL];
            if (FPL == 8) {
                float4 u0 = *(const float4*)h0;
                float4 u1 = *(const float4*)(h0 + 4);
                acc[0] = fmaf(a0, u0.x, acc[0]);
                acc[1] = fmaf(a0, u0.y, acc[1]);
                acc[2] = fmaf(a0, u0.z, acc[2]);
                acc[3] = fmaf(a0, u0.w, acc[3]);
                acc[4] = fmaf(a0, u1.x, acc[4]);
                acc[5] = fmaf(a0, u1.y, acc[5]);
                acc[6] = fmaf(a0, u1.z, acc[6]);
                acc[7] = fmaf(a0, u1.w, acc[7]);
            } else {
                float2 u = *(const float2*)h0;
                acc[0] = fmaf(a0, u.x, acc[0]);
                acc[1] = fmaf(a0, u.y, acc[1]);
            }
        }
    }

    // ---- bias + ELU + store ----
    size_t ob = (size_t)gw * F + lane * FPL;
#pragma unroll
    for (int i = 0; i < FPL; i++) {
        float v = acc[i] + bias[lane * FPL + i];
        if (apply_elu) v = (v > 0.f) ? v : expm1f(v);
        if (out_t) out_t[ob + i] = f2tf(v);
        else out[ob + i] = v;
    }
}

// ---------------- launcher ----------------
extern "C" void kernel_launch(void* const* d_in, const int* in_sizes, int n_in,
                              void* d_out, int out_size) {
    const float* x   = (const float*)d_in[0];
    const int*   ei  = (const int*)d_in[1];
    const float* W1  = (const float*)d_in[2];
    const float* as1 = (const float*)d_in[3];
    const float* ad1 = (const float*)d_in[4];
    const float* b1  = (const float*)d_in[5];
    const float* W2  = (const float*)d_in[6];
    const float* as2 = (const float*)d_in[7];
    const float* ad2 = (const float*)d_in[8];
    const float* b2  = (const float*)d_in[9];
    const float* W3  = (const float*)d_in[10];
    const float* as3 = (const float*)d_in[11];
    const float* ad3 = (const float*)d_in[12];
    const float* b3  = (const float*)d_in[13];
    float* out = (float*)d_out;

    int n = in_sizes[0] / 256;   // 50000
    int e = in_sizes[1] / 2;     // 320000

    float *bufA;
    uint32_t *bufBt, *xt, *w1t, *w2t, *w3t;
    cudaGetSymbolAddress((void**)&bufA, g_bufA);
    cudaGetSymbolAddress((void**)&bufBt, g_bufBt);
    cudaGetSymbolAddress((void**)&xt, g_xt);
    cudaGetSymbolAddress((void**)&w1t, g_w1t);
    cudaGetSymbolAddress((void**)&w2t, g_w2t);
    cudaGetSymbolAddress((void**)&w3t, g_w3t);

    int nb1 = (n + 1023) / 1024;
    int nrb = (n + 127) / 128;
    int nab = (n + 7) / 8;   // warp-per-dst agg blocks

    // side stream for CSR build, overlapped with preconvert + layer-1 GEMM.
    cudaStream_t s2;
    cudaStreamCreateWithFlags(&s2, cudaStreamNonBlocking);
    cudaEvent_t ev1, ev2;
    cudaEventCreateWithFlags(&ev1, cudaEventDisableTiming);
    cudaEventCreateWithFlags(&ev2, cudaEventDisableTiming);

    cudaEventRecord(ev1, 0);
    cudaStreamWaitEvent(s2, ev1, 0);

    // default stream: preconvert + layer-1 GEMM
    k_pre<<<512, 256>>>(x, W1, W2, W3, in_sizes[0] / 4, in_sizes[2], in_sizes[6],
                        in_sizes[10]);
    k_gemm_tc<<<dim3(2, nrb), 128>>>(xt, w1t, bufA, as1, ad1, n, 256, 256);

    // side stream: CSR build
    k_init<<<(n + 255) / 256, 256, 0, s2>>>(n);
    k_count<<<(e + 255) / 256, 256, 0, s2>>>(ei, e);
    k_scan1<<<nb1, 1024, 0, s2>>>(n);
    k_scan3m<<<nb1, 1024, 0, s2>>>(n);
    k_scatter<<<(e + n + 255) / 256, 256, 0, s2>>>(ei, e, n);
    cudaEventRecord(ev2, s2);

    // join: aggregation needs both GEMM-1 and CSR
    cudaStreamWaitEvent(0, ev2, 0);

    k_agg_w<256, 4><<<nab, 256>>>(bufA, b1, nullptr, bufBt, n, 1);
    k_gemm_tc<<<dim3(2, nrb), 128>>>(bufBt, w2t, bufA, as2, ad2, n, 256, 256);
    k_agg_w<256, 4><<<nab, 256>>>(bufA, b2, nullptr, bufBt, n, 1);
    k_gemm_tc<<<dim3(1, nrb), 128>>>(bufBt, w3t, bufA, as3, ad3, n, 256, 64);
    k_agg_w<64, 1><<<nab, 256>>>(bufA, b3, out, nullptr, n, 0);
}

// round 7
// speedup vs baseline: 3.8160x; 1.3665x over previous
#include <cuda_runtime.h>
#include <cuda_fp16.h>
#include <math.h>
#include <stdint.h>

// ---------------- static scratch (no allocation allowed) ----------------
#define N_CAP 65536
#define E_CAP (1 << 20)

__device__ __half g_bufAh[(size_t)N_CAP * 256];  // h of current layer (gemm out)
__device__ __half g_bufBh[(size_t)N_CAP * 256];  // agg output (gemm in)
__device__ __half g_xh[(size_t)N_CAP * 256];     // fp16 input x
__device__ __half g_w1h[65536];
__device__ __half g_w2h[65536];
__device__ __half g_w3h[16384];
__device__ float g_als[N_CAP * 4];
__device__ float g_ald[N_CAP * 4];
__device__ int   g_rowptr[N_CAP + 1];
__device__ int   g_wptr[N_CAP];
__device__ int   g_srcs[E_CAP];
__device__ int   g_bsum[80];

// ---------------- preconvert (vectorized) ----------------
__global__ void k_pre(const float* __restrict__ x, const float* __restrict__ W1,
                      const float* __restrict__ W2, const float* __restrict__ W3,
                      int nx4, int nw1, int nw2, int nw3) {
    int i = blockIdx.x * blockDim.x + threadIdx.x;
    int stride = gridDim.x * blockDim.x;
    const float4* x4 = (const float4*)x;
    uint2* xo = (uint2*)g_xh;
    for (int j = i; j < nx4; j += stride) {
        float4 v = x4[j];
        __half2 lo = __floats2half2_rn(v.x, v.y);
        __half2 hi = __floats2half2_rn(v.z, v.w);
        uint2 o;
        o.x = *(uint32_t*)&lo;
        o.y = *(uint32_t*)&hi;
        xo[j] = o;
    }
    for (int j = i; j < nw1; j += stride) g_w1h[j] = __float2half_rn(W1[j]);
    for (int j = i; j < nw2; j += stride) g_w2h[j] = __float2half_rn(W2[j]);
    for (int j = i; j < nw3; j += stride) g_w3h[j] = __float2half_rn(W3[j]);
}

// ---------------- CSR build ----------------
__global__ void k_init(int n) {
    int i = blockIdx.x * blockDim.x + threadIdx.x;
    if (i < n) g_wptr[i] = 1;  // self-loop pre-count
}

__global__ void k_count(const int* __restrict__ ei, int e) {
    int t = blockIdx.x * blockDim.x + threadIdx.x;
    if (t < e) atomicAdd(&g_wptr[ei[e + t]], 1);
}

__global__ void k_scan1(int n) {
    __shared__ int sm[1024];
    int t = threadIdx.x;
    int i = blockIdx.x * 1024 + t;
    int v = (i < n) ? g_wptr[i] : 0;
    sm[t] = v;
    __syncthreads();
    for (int off = 1; off < 1024; off <<= 1) {
        int x = (t >= off) ? sm[t - off] : 0;
        __syncthreads();
        sm[t] += x;
        __syncthreads();
    }
    if (i < n) g_rowptr[i + 1] = sm[t];
    if (t == 1023) g_bsum[blockIdx.x] = sm[1023];
}

__global__ void k_scan3m(int n) {
    __shared__ int s_off;
    int t = threadIdx.x, b = blockIdx.x;
    if (t < 32) {
        int acc = 0;
        for (int i = t; i < b; i += 32) acc += g_bsum[i];
#pragma unroll
        for (int o = 16; o; o >>= 1) acc += __shfl_down_sync(0xffffffffu, acc, o);
        if (t == 0) s_off = acc;
    }
    __syncthreads();
    int i = b * 1024 + t;
    if (i < n) {
        int v = g_rowptr[i + 1] + s_off;
        g_rowptr[i + 1] = v;
        if (i + 1 < n) g_wptr[i + 1] = v;
    }
    if (i == 0) { g_rowptr[0] = 0; g_wptr[0] = 0; }
}

__global__ void k_scatter(const int* __restrict__ ei, int e, int n) {
    int t = blockIdx.x * blockDim.x + threadIdx.x;
    if (t < e) {
        int src = ei[t];
        int dst = ei[e + t];
        int pos = atomicAdd(&g_wptr[dst], 1);
        g_srcs[pos] = src;
    } else if (t < e + n) {
        int i = t - e;
        int pos = atomicAdd(&g_wptr[i], 1);
        g_srcs[pos] = i;  // self loop
    }
}

// ---------------- cp.async / ldmatrix helpers ----------------
__device__ __forceinline__ void cp16(uint32_t dst, const void* src, int bytes) {
    asm volatile("cp.async.cg.shared.global [%0], [%1], 16, %2;"
                 :: "r"(dst), "l"(src), "r"(bytes));
}
__device__ __forceinline__ void cp_commit() { asm volatile("cp.async.commit_group;"); }
template <int NN> __device__ __forceinline__ void cp_wait() {
    asm volatile("cp.async.wait_group %0;" :: "n"(NN));
}
__device__ __forceinline__ void ldm4(uint32_t& r0, uint32_t& r1, uint32_t& r2,
                                     uint32_t& r3, uint32_t addr) {
    asm volatile("ldmatrix.sync.aligned.m8n8.x4.shared.b16 {%0,%1,%2,%3}, [%4];"
                 : "=r"(r0), "=r"(r1), "=r"(r2), "=r"(r3) : "r"(addr));
}
__device__ __forceinline__ void ldm4t(uint32_t& r0, uint32_t& r1, uint32_t& r2,
                                      uint32_t& r3, uint32_t addr) {
    asm volatile("ldmatrix.sync.aligned.m8n8.x4.trans.shared.b16 {%0,%1,%2,%3}, [%4];"
                 : "=r"(r0), "=r"(r1), "=r"(r2), "=r"(r3) : "r"(addr));
}

// ---------------- fp16 tensor-core GEMM + fused attention logits ----------------
// C[n,M] = A[n,K] @ B[K,M], fp16 in, fp32 acc, fp16 C out. Tile 128x128, BK=32.
// 8 warps 4x2, warp tile 32x64, mma m16n8k16 via ldmatrix.
#define ASTR 40   // A smem row stride (halves): 32 + 8 pad
#define BSTR 136  // B smem row stride (halves): 128 + 8 pad

__global__ __launch_bounds__(256) void k_gemm_tc(const __half* __restrict__ A,
                                                 const __half* __restrict__ B,
                                                 __half* __restrict__ C,
                                                 const float* __restrict__ a_s,
                                                 const float* __restrict__ a_d,
                                                 int n, int K, int M) {
    __shared__ __half As[2][128][ASTR];
    __shared__ __half Bs[2][32][BSTR];
    __shared__ float s_als[128][2], s_ald[128][2];
    __shared__ float s_as[128], s_ad[128];

    int tid = threadIdx.x, lane = tid & 31, warp = tid >> 5;
    int wm = warp >> 1, wn = warp & 1;   // 4 x 2 warp grid, 32x64 each
    int r0 = blockIdx.y * 128, c0 = blockIdx.x * 128;

    uint32_t as_base = (uint32_t)__cvta_generic_to_shared(&As[0][0][0]);
    uint32_t bs_base = (uint32_t)__cvta_generic_to_shared(&Bs[0][0][0]);

    if (tid < 128 && c0 + tid < M) {
        s_as[tid] = a_s[c0 + tid];
        s_ad[tid] = a_d[c0 + tid];
    }

    float acc[2][8][4];
#pragma unroll
    for (int mt = 0; mt < 2; mt++)
#pragma unroll
        for (int nt = 0; nt < 8; nt++)
#pragma unroll
            for (int i = 0; i < 4; i++) acc[mt][nt][i] = 0.f;

    int KT = K >> 5;  // BK = 32

    // A: 128 rows x 64B -> 512 16B-chunks, 2/thread. B: 32 rows x 256B -> 512, 2/thread.
#define LOAD_TILE(KT_IDX, BUF)                                                      \
    {                                                                               \
        int k0 = (KT_IDX) << 5;                                                     \
        _Pragma("unroll")                                                           \
        for (int i = 0; i < 2; i++) {                                               \
            int row = (tid >> 2) + 64 * i;                                          \
            int ac = (tid & 3) * 8;                                                 \
            int gr = r0 + row;                                                      \
            const __half* src = A + (size_t)(gr < n ? gr : 0) * K + k0 + ac;        \
            cp16(as_base + ((BUF) * 128 + row) * (ASTR * 2) + ac * 2, src,          \
                 gr < n ? 16 : 0);                                                  \
        }                                                                           \
        _Pragma("unroll")                                                           \
        for (int i = 0; i < 2; i++) {                                               \
            int rr = (tid >> 4) + 16 * i;                                           \
            int bc = (tid & 15) * 8;                                                \
            int gc = c0 + bc;                                                       \
            const __half* src = B + (size_t)(k0 + rr) * M + (gc < M ? gc : 0);      \
            cp16(bs_base + ((BUF) * 32 + rr) * (BSTR * 2) + bc * 2, src,            \
                 gc < M ? 16 : 0);                                                  \
        }                                                                           \
    }

    LOAD_TILE(0, 0);
    cp_commit();

    for (int kt = 0; kt < KT; kt++) {
        int buf = kt & 1;
        if (kt + 1 < KT) {
            LOAD_TILE(kt + 1, buf ^ 1);
            cp_commit();
            cp_wait<1>();
        } else {
            cp_wait<0>();
        }
        __syncthreads();

#pragma unroll
        for (int ks = 0; ks < 2; ks++) {
            int kb = ks * 16;
            uint32_t a[2][4], b[8][2];
#pragma unroll
            for (int mt = 0; mt < 2; mt++) {
                int row = wm * 32 + mt * 16 + (lane & 15);
                int col = kb + ((lane & 16) ? 8 : 0);
                uint32_t addr = as_base + (buf * 128 + row) * (ASTR * 2) + col * 2;
                ldm4(a[mt][0], a[mt][1], a[mt][2], a[mt][3], addr);
            }
#pragma unroll
            for (int g = 0; g < 4; g++) {
                int row = kb + (lane & 15);
                int col = wn * 64 + g * 16 + ((lane & 16) ? 8 : 0);
                uint32_t addr = bs_base + (buf * 32 + row) * (BSTR * 2) + col * 2;
                ldm4t(b[g * 2][0], b[g * 2][1], b[g * 2 + 1][0], b[g * 2 + 1][1], addr);
            }
#pragma unroll
            for (int mt = 0; mt < 2; mt++)
#pragma unroll
                for (int nt = 0; nt < 8; nt++) {
                    asm volatile(
                        "mma.sync.aligned.m16n8k16.row.col.f32.f16.f16.f32 "
                        "{%0,%1,%2,%3}, {%4,%5,%6,%7}, {%8,%9}, {%0,%1,%2,%3};"
                        : "+f"(acc[mt][nt][0]), "+f"(acc[mt][nt][1]),
                          "+f"(acc[mt][nt][2]), "+f"(acc[mt][nt][3])
                        : "r"(a[mt][0]), "r"(a[mt][1]), "r"(a[mt][2]), "r"(a[mt][3]),
                          "r"(b[nt][0]), "r"(b[nt][1]));
                }
        }
        __syncthreads();
    }

    // ---- fused attention-logit epilogue + C store (fp16) ----
    bool colok = (c0 + wn * 64) < M;
    if (colok) {
#pragma unroll
        for (int mt = 0; mt < 2; mt++) {
#pragma unroll
            for (int rr = 0; rr < 2; rr++) {
                float ps = 0.f, pd = 0.f;
#pragma unroll
                for (int nt = 0; nt < 8; nt++)
#pragma unroll
                    for (int q = 0; q < 2; q++) {
                        int lc = nt * 8 + (lane & 3) * 2 + q;
                        float v = acc[mt][nt][rr * 2 + q];
                        ps = fmaf(v, s_as[wn * 64 + lc], ps);
                        pd = fmaf(v, s_ad[wn * 64 + lc], pd);
                    }
                ps += __shfl_down_sync(0xffffffffu, ps, 1);
                ps += __shfl_down_sync(0xffffffffu, ps, 2);
                pd += __shfl_down_sync(0xffffffffu, pd, 1);
                pd += __shfl_down_sync(0xffffffffu, pd, 2);
                if ((lane & 3) == 0) {
                    int rl = wm * 32 + mt * 16 + (lane >> 2) + rr * 8;
                    s_als[rl][wn] = ps;
                    s_ald[rl][wn] = pd;
                }
            }
        }
#pragma unroll
        for (int mt = 0; mt < 2; mt++) {
            int row = r0 + wm * 32 + mt * 16 + (lane >> 2);
#pragma unroll
            for (int nt = 0; nt < 8; nt++) {
                int col = c0 + wn * 64 + nt * 8 + (lane & 3) * 2;
                if (row < n) {
                    __half2 v = __floats2half2_rn(acc[mt][nt][0], acc[mt][nt][1]);
                    *(uint32_t*)&C[(size_t)row * M + col] = *(uint32_t*)&v;
                }
                if (row + 8 < n) {
                    __half2 v = __floats2half2_rn(acc[mt][nt][2], acc[mt][nt][3]);
                    *(uint32_t*)&C[(size_t)(row + 8) * M + col] = *(uint32_t*)&v;
                }
            }
        }
    }
    __syncthreads();

    if (tid < 128) {
        int row = r0 + tid;
        if (row < n) {
            int hb = c0 >> 6;
            g_als[row * 4 + hb] = s_als[tid][0];
            g_ald[row * 4 + hb] = s_ald[tid][0];
            if (c0 + 64 < M) {
                g_als[row * 4 + hb + 1] = s_als[tid][1];
                g_ald[row * 4 + hb + 1] = s_ald[tid][1];
            }
        }
    }
}

// ---------------- aggregation: one WARP per dst node (fp16 features) ----------------
template <int F, int H>
__global__ __launch_bounds__(256) void k_agg_w(const __half* __restrict__ h,
                                               const float* __restrict__ bias,
                                               float* __restrict__ out,
                                               __half* __restrict__ out_h,
                                               int n, int apply_elu) {
    int gw = (blockIdx.x * 256 + threadIdx.x) >> 5;
    int lane = threadIdx.x & 31;
    if (gw >= n) return;
    constexpr int FPL = F / 32;       // 8 or 2
    constexpr int CH = F / H;         // channels per head (64)
    int hh = (lane * FPL) / CH;       // this lane's head

    int r0 = g_rowptr[gw];
    int deg = g_rowptr[gw + 1] - r0;

    float4 aldv = *(const float4*)&g_ald[gw * 4];
    float ald[4] = {aldv.x, aldv.y, aldv.z, aldv.w};

    // ---- online softmax stats ----
    float m[H], sa[H];
#pragma unroll
    for (int i = 0; i < H; i++) { m[i] = -1e30f; sa[i] = 0.f; }
    for (int j = lane; j < deg; j += 32) {
        int src = __ldg(&g_srcs[r0 + j]);
        float4 alv = *(const float4*)&g_als[src * 4];
        float al[4] = {alv.x, alv.y, alv.z, alv.w};
#pragma unroll
        for (int i = 0; i < H; i++) {
            float l = al[i] + ald[i];
            l = (l < 0.f) ? 0.2f * l : l;
            float nm = fmaxf(m[i], l);
            sa[i] = sa[i] * __expf(m[i] - nm) + __expf(l - nm);
            m[i] = nm;
        }
    }
#pragma unroll
    for (int o = 16; o; o >>= 1) {
#pragma unroll
        for (int i = 0; i < H; i++) {
            float mo = __shfl_xor_sync(0xffffffffu, m[i], o);
            float so = __shfl_xor_sync(0xffffffffu, sa[i], o);
            float nm = fmaxf(m[i], mo);
            sa[i] = sa[i] * __expf(m[i] - nm) + so * __expf(mo - nm);
            m[i] = nm;
        }
    }
    float mh = m[hh];
    float invh = 1.f / (sa[hh] + 1e-16f);
    float aldh = ald[hh];

    // ---- weighted feature gather (fp16 loads, unrolled x2) ----
    float acc[FPL];
#pragma unroll
    for (int i = 0; i < FPL; i++) acc[i] = 0.f;

    for (int base = 0; base < deg; base += 32) {
        int cnt = min(32, deg - base);
        int mysrc = (base + lane < deg) ? g_srcs[r0 + base + lane] : 0;
        int jj = 0;
        for (; jj + 2 <= cnt; jj += 2) {
            int s0 = __shfl_sync(0xffffffffu, mysrc, jj);
            int s1 = __shfl_sync(0xffffffffu, mysrc, jj + 1);
            float l0 = g_als[s0 * 4 + hh] + aldh;
            float l1 = g_als[s1 * 4 + hh] + aldh;
            l0 = (l0 < 0.f) ? 0.2f * l0 : l0;
            l1 = (l1 < 0.f) ? 0.2f * l1 : l1;
            float a0 = __expf(l0 - mh) * invh;
            float a1 = __expf(l1 - mh) * invh;
            const __half* h0 = h + (size_t)s0 * F + lane * FPL;
            const __half* h1 = h + (size_t)s1 * F + lane * FPL;
            if (FPL == 8) {
                uint4 u = *(const uint4*)h0;
                uint4 w = *(const uint4*)h1;
                const __half2* uh = (const __half2*)&u;
                const __half2* wh = (const __half2*)&w;
#pragma unroll
                for (int q = 0; q < 4; q++) {
                    float2 uf = __half22float2(uh[q]);
                    float2 wf = __half22float2(wh[q]);
                    acc[q * 2 + 0] = fmaf(a0, uf.x, fmaf(a1, wf.x, acc[q * 2 + 0]));
                    acc[q * 2 + 1] = fmaf(a0, uf.y, fmaf(a1, wf.y, acc[q * 2 + 1]));
                }
            } else {
                float2 uf = __half22float2(*(const __half2*)h0);
                float2 wf = __half22float2(*(const __half2*)h1);
                acc[0] = fmaf(a0, uf.x, fmaf(a1, wf.x, acc[0]));
                acc[1] = fmaf(a0, uf.y, fmaf(a1, wf.y, acc[1]));
            }
        }
        if (jj < cnt) {
            int s0 = __shfl_sync(0xffffffffu, mysrc, jj);
            float l0 = g_als[s0 * 4 + hh] + aldh;
            l0 = (l0 < 0.f) ? 0.2f * l0 : l0;
            float a0 = __expf(l0 - mh) * invh;
            const __half* h0 = h + (size_t)s0 * F + lane * FPL;
            if (FPL == 8) {
                uint4 u = *(const uint4*)h0;
                const __half2* uh = (const __half2*)&u;
#pragma unroll
                for (int q = 0; q < 4; q++) {
                    float2 uf = __half22float2(uh[q]);
                    acc[q * 2 + 0] = fmaf(a0, uf.x, acc[q * 2 + 0]);
                    acc[q * 2 + 1] = fmaf(a0, uf.y, acc[q * 2 + 1]);
                }
            } else {
                float2 uf = __half22float2(*(const __half2*)h0);
                acc[0] = fmaf(a0, uf.x, acc[0]);
                acc[1] = fmaf(a0, uf.y, acc[1]);
            }
        }
    }

    // ---- bias + ELU + store ----
    size_t ob = (size_t)gw * F + lane * FPL;
#pragma unroll
    for (int i = 0; i < FPL; i++) {
        float v = acc[i] + bias[lane * FPL + i];
        if (apply_elu) v = (v > 0.f) ? v : expm1f(v);
        if (out_h) out_h[ob + i] = __float2half_rn(v);
        else out[ob + i] = v;
    }
}

// ---------------- launcher ----------------
extern "C" void kernel_launch(void* const* d_in, const int* in_sizes, int n_in,
                              void* d_out, int out_size) {
    const float* x   = (const float*)d_in[0];
    const int*   ei  = (const int*)d_in[1];
    const float* W1  = (const float*)d_in[2];
    const float* as1 = (const float*)d_in[3];
    const float* ad1 = (const float*)d_in[4];
    const float* b1  = (const float*)d_in[5];
    const float* W2  = (const float*)d_in[6];
    const float* as2 = (const float*)d_in[7];
    const float* ad2 = (const float*)d_in[8];
    const float* b2  = (const float*)d_in[9];
    const float* W3  = (const float*)d_in[10];
    const float* as3 = (const float*)d_in[11];
    const float* ad3 = (const float*)d_in[12];
    const float* b3  = (const float*)d_in[13];
    float* out = (float*)d_out;

    int n = in_sizes[0] / 256;   // 50000
    int e = in_sizes[1] / 2;     // 320000

    __half *bufA, *bufB, *xh, *w1h, *w2h, *w3h;
    cudaGetSymbolAddress((void**)&bufA, g_bufAh);
    cudaGetSymbolAddress((void**)&bufB, g_bufBh);
    cudaGetSymbolAddress((void**)&xh, g_xh);
    cudaGetSymbolAddress((void**)&w1h, g_w1h);
    cudaGetSymbolAddress((void**)&w2h, g_w2h);
    cudaGetSymbolAddress((void**)&w3h, g_w3h);

    int nb1 = (n + 1023) / 1024;
    int nrb = (n + 127) / 128;
    int nab = (n + 7) / 8;

    // side stream for CSR build, overlapped with preconvert + layer-1 GEMM.
    cudaStream_t s2;
    cudaStreamCreateWithFlags(&s2, cudaStreamNonBlocking);
    cudaEvent_t ev1, ev2;
    cudaEventCreateWithFlags(&ev1, cudaEventDisableTiming);
    cudaEventCreateWithFlags(&ev2, cudaEventDisableTiming);

    cudaEventRecord(ev1, 0);
    cudaStreamWaitEvent(s2, ev1, 0);

    // default stream: preconvert + layer-1 GEMM
    k_pre<<<512, 256>>>(x, W1, W2, W3, in_sizes[0] / 4, in_sizes[2], in_sizes[6],
                        in_sizes[10]);
    k_gemm_tc<<<dim3(2, nrb), 256>>>(xh, w1h, bufA, as1, ad1, n, 256, 256);

    // side stream: CSR build
    k_init<<<(n + 255) / 256, 256, 0, s2>>>(n);
    k_count<<<(e + 255) / 256, 256, 0, s2>>>(ei, e);
    k_scan1<<<nb1, 1024, 0, s2>>>(n);
    k_scan3m<<<nb1, 1024, 0, s2>>>(n);
    k_scatter<<<(e + n + 255) / 256, 256, 0, s2>>>(ei, e, n);
    cudaEventRecord(ev2, s2);

    // join: aggregation needs both GEMM-1 and CSR
    cudaStreamWaitEvent(0, ev2, 0);

    k_agg_w<256, 4><<<nab, 256>>>(bufA, b1, nullptr, bufB, n, 1);
    k_gemm_tc<<<dim3(2, nrb), 256>>>(bufB, w2h, bufA, as2, ad2, n, 256, 256);
    k_agg_w<256, 4><<<nab, 256>>>(bufA, b2, nullptr, bufB, n, 1);
    k_gemm_tc<<<dim3(1, nrb), 256>>>(bufB, w3h, bufA, as3, ad3, n, 256, 64);
    k_agg_w<64, 1><<<nab, 256>>>(bufA, b3, out, nullptr, n, 0);
}

// round 8
// speedup vs baseline: 3.8779x; 1.0162x over previous
#include <cuda_runtime.h>
#include <cuda_fp16.h>
#include <math.h>
#include <stdint.h>

// ---------------- static scratch (no allocation allowed) ----------------
#define N_CAP 65536
#define E_CAP (1 << 20)

__device__ __half g_bufAh[(size_t)N_CAP * 256];  // h of current layer (gemm out)
__device__ __half g_bufBh[(size_t)N_CAP * 256];  // agg output (gemm in)
__device__ __half g_xh[(size_t)N_CAP * 256];     // fp16 input x
__device__ __half g_w1h[65536];
__device__ __half g_w2h[65536];
__device__ __half g_w3h[16384];
__device__ float g_als[N_CAP * 4];
__device__ float g_ald[N_CAP * 4];
__device__ int   g_rowptr[N_CAP + 1];
__device__ int   g_wptr[N_CAP];
__device__ int   g_srcs[E_CAP];
__device__ int   g_bsum[80];

// ---------------- preconvert ----------------
__global__ void k_prew(const float* __restrict__ W1, const float* __restrict__ W2,
                       const float* __restrict__ W3, int nw1, int nw2, int nw3) {
    int i = blockIdx.x * blockDim.x + threadIdx.x;
    int stride = gridDim.x * blockDim.x;
    for (int j = i; j < nw1; j += stride) g_w1h[j] = __float2half_rn(W1[j]);
    for (int j = i; j < nw2; j += stride) g_w2h[j] = __float2half_rn(W2[j]);
    for (int j = i; j < nw3; j += stride) g_w3h[j] = __float2half_rn(W3[j]);
}

__global__ void k_prex(const float* __restrict__ x, int nx4) {
    int i = blockIdx.x * blockDim.x + threadIdx.x;
    int stride = gridDim.x * blockDim.x;
    const float4* x4 = (const float4*)x;
    uint2* xo = (uint2*)g_xh;
    for (int j = i; j < nx4; j += stride) {
        float4 v = x4[j];
        __half2 lo = __floats2half2_rn(v.x, v.y);
        __half2 hi = __floats2half2_rn(v.z, v.w);
        uint2 o;
        o.x = *(uint32_t*)&lo;
        o.y = *(uint32_t*)&hi;
        xo[j] = o;
    }
}

// ---------------- CSR build ----------------
__global__ void k_init(int n) {
    int i = blockIdx.x * blockDim.x + threadIdx.x;
    if (i < n) g_wptr[i] = 1;  // self-loop pre-count
}

__global__ void k_count(const int* __restrict__ ei, int e) {
    int t = blockIdx.x * blockDim.x + threadIdx.x;
    if (t < e) atomicAdd(&g_wptr[ei[e + t]], 1);
}

__global__ void k_scan1(int n) {
    __shared__ int sm[1024];
    int t = threadIdx.x;
    int i = blockIdx.x * 1024 + t;
    int v = (i < n) ? g_wptr[i] : 0;
    sm[t] = v;
    __syncthreads();
    for (int off = 1; off < 1024; off <<= 1) {
        int x = (t >= off) ? sm[t - off] : 0;
        __syncthreads();
        sm[t] += x;
        __syncthreads();
    }
    if (i < n) g_rowptr[i + 1] = sm[t];
    if (t == 1023) g_bsum[blockIdx.x] = sm[1023];
}

__global__ void k_scan3m(int n) {
    __shared__ int s_off;
    int t = threadIdx.x, b = blockIdx.x;
    if (t < 32) {
        int acc = 0;
        for (int i = t; i < b; i += 32) acc += g_bsum[i];
#pragma unroll
        for (int o = 16; o; o >>= 1) acc += __shfl_down_sync(0xffffffffu, acc, o);
        if (t == 0) s_off = acc;
    }
    __syncthreads();
    int i = b * 1024 + t;
    if (i < n) {
        int v = g_rowptr[i + 1] + s_off;
        g_rowptr[i + 1] = v;
        if (i + 1 < n) g_wptr[i + 1] = v;
    }
    if (i == 0) { g_rowptr[0] = 0; g_wptr[0] = 0; }
}

__global__ void k_scatter(const int* __restrict__ ei, int e, int n) {
    int t = blockIdx.x * blockDim.x + threadIdx.x;
    if (t < e) {
        int src = ei[t];
        int dst = ei[e + t];
        int pos = atomicAdd(&g_wptr[dst], 1);
        g_srcs[pos] = src;
    } else if (t < e + n) {
        int i = t - e;
        int pos = atomicAdd(&g_wptr[i], 1);
        g_srcs[pos] = i;  // self loop
    }
}

// ---------------- cp.async / ldmatrix helpers ----------------
__device__ __forceinline__ void cp16(uint32_t dst, const void* src, int bytes) {
    asm volatile("cp.async.cg.shared.global [%0], [%1], 16, %2;"
                 :: "r"(dst), "l"(src), "r"(bytes));
}
__device__ __forceinline__ void cp_commit() { asm volatile("cp.async.commit_group;"); }
template <int NN> __device__ __forceinline__ void cp_wait() {
    asm volatile("cp.async.wait_group %0;" :: "n"(NN));
}
__device__ __forceinline__ void ldm4(uint32_t& r0, uint32_t& r1, uint32_t& r2,
                                     uint32_t& r3, uint32_t addr) {
    asm volatile("ldmatrix.sync.aligned.m8n8.x4.shared.b16 {%0,%1,%2,%3}, [%4];"
                 : "=r"(r0), "=r"(r1), "=r"(r2), "=r"(r3) : "r"(addr));
}
__device__ __forceinline__ void ldm4t(uint32_t& r0, uint32_t& r1, uint32_t& r2,
                                      uint32_t& r3, uint32_t addr) {
    asm volatile("ldmatrix.sync.aligned.m8n8.x4.trans.shared.b16 {%0,%1,%2,%3}, [%4];"
                 : "=r"(r0), "=r"(r1), "=r"(r2), "=r"(r3) : "r"(addr));
}

// ---------------- fp16 tensor-core GEMM + fused attention logits ----------------
// C[n,M] = A[n,K] @ B[K,M], fp16 in, fp32 acc, fp16 C out. Tile 128x128, BK=32.
// 8 warps 4x2, warp tile 32x64, mma m16n8k16 via ldmatrix.
#define ASTR 40   // A smem row stride (halves): 32 + 8 pad
#define BSTR 136  // B smem row stride (halves): 128 + 8 pad

__global__ __launch_bounds__(256, 2) void k_gemm_tc(const __half* __restrict__ A,
                                                    const __half* __restrict__ B,
                                                    __half* __restrict__ C,
                                                    const float* __restrict__ a_s,
                                                    const float* __restrict__ a_d,
                                                    int n, int K, int M) {
    __shared__ __half As[2][128][ASTR];
    __shared__ __half Bs[2][32][BSTR];
    __shared__ float s_als[128][2], s_ald[128][2];
    __shared__ float s_as[128], s_ad[128];

    int tid = threadIdx.x, lane = tid & 31, warp = tid >> 5;
    int wm = warp >> 1, wn = warp & 1;   // 4 x 2 warp grid, 32x64 each
    int r0 = blockIdx.y * 128, c0 = blockIdx.x * 128;

    uint32_t as_base = (uint32_t)__cvta_generic_to_shared(&As[0][0][0]);
    uint32_t bs_base = (uint32_t)__cvta_generic_to_shared(&Bs[0][0][0]);

    if (tid < 128 && c0 + tid < M) {
        s_as[tid] = a_s[c0 + tid];
        s_ad[tid] = a_d[c0 + tid];
    }

    float acc[2][8][4];
#pragma unroll
    for (int mt = 0; mt < 2; mt++)
#pragma unroll
        for (int nt = 0; nt < 8; nt++)
#pragma unroll
            for (int i = 0; i < 4; i++) acc[mt][nt][i] = 0.f;

    int KT = K >> 5;  // BK = 32

#define LOAD_TILE(KT_IDX, BUF)                                                      \
    {                                                                               \
        int k0 = (KT_IDX) << 5;                                                     \
        _Pragma("unroll")                                                           \
        for (int i = 0; i < 2; i++) {                                               \
            int row = (tid >> 2) + 64 * i;                                          \
            int ac = (tid & 3) * 8;                                                 \
            int gr = r0 + row;                                                      \
            const __half* src = A + (size_t)(gr < n ? gr : 0) * K + k0 + ac;        \
            cp16(as_base + ((BUF) * 128 + row) * (ASTR * 2) + ac * 2, src,          \
                 gr < n ? 16 : 0);                                                  \
        }                                                                           \
        _Pragma("unroll")                                                           \
        for (int i = 0; i < 2; i++) {                                               \
            int rr = (tid >> 4) + 16 * i;                                           \
            int bc = (tid & 15) * 8;                                                \
            int gc = c0 + bc;                                                       \
            const __half* src = B + (size_t)(k0 + rr) * M + (gc < M ? gc : 0);      \
            cp16(bs_base + ((BUF) * 32 + rr) * (BSTR * 2) + bc * 2, src,            \
                 gc < M ? 16 : 0);                                                  \
        }                                                                           \
    }

    LOAD_TILE(0, 0);
    cp_commit();

    for (int kt = 0; kt < KT; kt++) {
        int buf = kt & 1;
        if (kt + 1 < KT) {
            LOAD_TILE(kt + 1, buf ^ 1);
            cp_commit();
            cp_wait<1>();
        } else {
            cp_wait<0>();
        }
        __syncthreads();

#pragma unroll
        for (int ks = 0; ks < 2; ks++) {
            int kb = ks * 16;
            uint32_t a[2][4], b[8][2];
#pragma unroll
            for (int mt = 0; mt < 2; mt++) {
                int row = wm * 32 + mt * 16 + (lane & 15);
                int col = kb + ((lane & 16) ? 8 : 0);
                uint32_t addr = as_base + (buf * 128 + row) * (ASTR * 2) + col * 2;
                ldm4(a[mt][0], a[mt][1], a[mt][2], a[mt][3], addr);
            }
#pragma unroll
            for (int g = 0; g < 4; g++) {
                int row = kb + (lane & 15);
                int col = wn * 64 + g * 16 + ((lane & 16) ? 8 : 0);
                uint32_t addr = bs_base + (buf * 32 + row) * (BSTR * 2) + col * 2;
                ldm4t(b[g * 2][0], b[g * 2][1], b[g * 2 + 1][0], b[g * 2 + 1][1], addr);
            }
#pragma unroll
            for (int mt = 0; mt < 2; mt++)
#pragma unroll
                for (int nt = 0; nt < 8; nt++) {
                    asm volatile(
                        "mma.sync.aligned.m16n8k16.row.col.f32.f16.f16.f32 "
                        "{%0,%1,%2,%3}, {%4,%5,%6,%7}, {%8,%9}, {%0,%1,%2,%3};"
                        : "+f"(acc[mt][nt][0]), "+f"(acc[mt][nt][1]),
                          "+f"(acc[mt][nt][2]), "+f"(acc[mt][nt][3])
                        : "r"(a[mt][0]), "r"(a[mt][1]), "r"(a[mt][2]), "r"(a[mt][3]),
                          "r"(b[nt][0]), "r"(b[nt][1]));
                }
        }
        __syncthreads();
    }

    // ---- fused attention-logit epilogue + C store (fp16) ----
    bool colok = (c0 + wn * 64) < M;
    if (colok) {
#pragma unroll
        for (int mt = 0; mt < 2; mt++) {
#pragma unroll
            for (int rr = 0; rr < 2; rr++) {
                float ps = 0.f, pd = 0.f;
#pragma unroll
                for (int nt = 0; nt < 8; nt++)
#pragma unroll
                    for (int q = 0; q < 2; q++) {
                        int lc = nt * 8 + (lane & 3) * 2 + q;
                        float v = acc[mt][nt][rr * 2 + q];
                        ps = fmaf(v, s_as[wn * 64 + lc], ps);
                        pd = fmaf(v, s_ad[wn * 64 + lc], pd);
                    }
                ps += __shfl_down_sync(0xffffffffu, ps, 1);
                ps += __shfl_down_sync(0xffffffffu, ps, 2);
                pd += __shfl_down_sync(0xffffffffu, pd, 1);
                pd += __shfl_down_sync(0xffffffffu, pd, 2);
                if ((lane & 3) == 0) {
                    int rl = wm * 32 + mt * 16 + (lane >> 2) + rr * 8;
                    s_als[rl][wn] = ps;
                    s_ald[rl][wn] = pd;
                }
            }
        }
#pragma unroll
        for (int mt = 0; mt < 2; mt++) {
            int row = r0 + wm * 32 + mt * 16 + (lane >> 2);
#pragma unroll
            for (int nt = 0; nt < 8; nt++) {
                int col = c0 + wn * 64 + nt * 8 + (lane & 3) * 2;
                if (row < n) {
                    __half2 v = __floats2half2_rn(acc[mt][nt][0], acc[mt][nt][1]);
                    *(uint32_t*)&C[(size_t)row * M + col] = *(uint32_t*)&v;
                }
                if (row + 8 < n) {
                    __half2 v = __floats2half2_rn(acc[mt][nt][2], acc[mt][nt][3]);
                    *(uint32_t*)&C[(size_t)(row + 8) * M + col] = *(uint32_t*)&v;
                }
            }
        }
    }
    __syncthreads();

    if (tid < 128) {
        int row = r0 + tid;
        if (row < n) {
            int hb = c0 >> 6;
            g_als[row * 4 + hb] = s_als[tid][0];
            g_ald[row * 4 + hb] = s_ald[tid][0];
            if (c0 + 64 < M) {
                g_als[row * 4 + hb + 1] = s_als[tid][1];
                g_ald[row * 4 + hb + 1] = s_ald[tid][1];
            }
        }
    }
}

// ---------------- aggregation: one WARP per dst node (fp16 features) ----------------
template <int F, int H>
__global__ __launch_bounds__(256) void k_agg_w(const __half* __restrict__ h,
                                               const float* __restrict__ bias,
                                               float* __restrict__ out,
                                               __half* __restrict__ out_h,
                                               int n, int apply_elu) {
    int gw = (blockIdx.x * 256 + threadIdx.x) >> 5;
    int lane = threadIdx.x & 31;
    if (gw >= n) return;
    constexpr int FPL = F / 32;       // 8 or 2
    constexpr int CH = F / H;         // channels per head (64)
    int hh = (lane * FPL) / CH;       // this lane's head

    int r0 = g_rowptr[gw];
    int deg = g_rowptr[gw + 1] - r0;

    float4 aldv = *(const float4*)&g_ald[gw * 4];
    float ald[4] = {aldv.x, aldv.y, aldv.z, aldv.w};

    // ---- online softmax stats ----
    float m[H], sa[H];
#pragma unroll
    for (int i = 0; i < H; i++) { m[i] = -1e30f; sa[i] = 0.f; }
    for (int j = lane; j < deg; j += 32) {
        int src = __ldg(&g_srcs[r0 + j]);
        float4 alv = *(const float4*)&g_als[src * 4];
        float al[4] = {alv.x, alv.y, alv.z, alv.w};
#pragma unroll
        for (int i = 0; i < H; i++) {
            float l = al[i] + ald[i];
            l = (l < 0.f) ? 0.2f * l : l;
            float nm = fmaxf(m[i], l);
            sa[i] = sa[i] * __expf(m[i] - nm) + __expf(l - nm);
            m[i] = nm;
        }
    }
#pragma unroll
    for (int o = 16; o; o >>= 1) {
#pragma unroll
        for (int i = 0; i < H; i++) {
            float mo = __shfl_xor_sync(0xffffffffu, m[i], o);
            float so = __shfl_xor_sync(0xffffffffu, sa[i], o);
            float nm = fmaxf(m[i], mo);
            sa[i] = sa[i] * __expf(m[i] - nm) + so * __expf(mo - nm);
            m[i] = nm;
        }
    }
    float mh = m[hh];
    float invh = 1.f / (sa[hh] + 1e-16f);
    float aldh = ald[hh];

    // ---- weighted feature gather (fp16 loads, unrolled x2) ----
    float acc[FPL];
#pragma unroll
    for (int i = 0; i < FPL; i++) acc[i] = 0.f;

    for (int base = 0; base < deg; base += 32) {
        int cnt = min(32, deg - base);
        int mysrc = (base + lane < deg) ? g_srcs[r0 + base + lane] : 0;
        int jj = 0;
        for (; jj + 2 <= cnt; jj += 2) {
            int s0 = __shfl_sync(0xffffffffu, mysrc, jj);
            int s1 = __shfl_sync(0xffffffffu, mysrc, jj + 1);
            float l0 = g_als[s0 * 4 + hh] + aldh;
            float l1 = g_als[s1 * 4 + hh] + aldh;
            l0 = (l0 < 0.f) ? 0.2f * l0 : l0;
            l1 = (l1 < 0.f) ? 0.2f * l1 : l1;
            float a0 = __expf(l0 - mh) * invh;
            float a1 = __expf(l1 - mh) * invh;
            const __half* h0 = h + (size_t)s0 * F + lane * FPL;
            const __half* h1 = h + (size_t)s1 * F + lane * FPL;
            if (FPL == 8) {
                uint4 u = *(const uint4*)h0;
                uint4 w = *(const uint4*)h1;
                const __half2* uh = (const __half2*)&u;
                const __half2* wh = (const __half2*)&w;
#pragma unroll
                for (int q = 0; q < 4; q++) {
                    float2 uf = __half22float2(uh[q]);
                    float2 wf = __half22float2(wh[q]);
                    acc[q * 2 + 0] = fmaf(a0, uf.x, fmaf(a1, wf.x, acc[q * 2 + 0]));
                    acc[q * 2 + 1] = fmaf(a0, uf.y, fmaf(a1, wf.y, acc[q * 2 + 1]));
                }
            } else {
                float2 uf = __half22float2(*(const __half2*)h0);
                float2 wf = __half22float2(*(const __half2*)h1);
                acc[0] = fmaf(a0, uf.x, fmaf(a1, wf.x, acc[0]));
                acc[1] = fmaf(a0, uf.y, fmaf(a1, wf.y, acc[1]));
            }
        }
        if (jj < cnt) {
            int s0 = __shfl_sync(0xffffffffu, mysrc, jj);
            float l0 = g_als[s0 * 4 + hh] + aldh;
            l0 = (l0 < 0.f) ? 0.2f * l0 : l0;
            float a0 = __expf(l0 - mh) * invh;
            const __half* h0 = h + (size_t)s0 * F + lane * FPL;
            if (FPL == 8) {
                uint4 u = *(const uint4*)h0;
                const __half2* uh = (const __half2*)&u;
#pragma unroll
                for (int q = 0; q < 4; q++) {
                    float2 uf = __half22float2(uh[q]);
                    acc[q * 2 + 0] = fmaf(a0, uf.x, acc[q * 2 + 0]);
                    acc[q * 2 + 1] = fmaf(a0, uf.y, acc[q * 2 + 1]);
                }
            } else {
                float2 uf = __half22float2(*(const __half2*)h0);
                acc[0] = fmaf(a0, uf.x, acc[0]);
                acc[1] = fmaf(a0, uf.y, acc[1]);
            }
        }
    }

    // ---- bias + ELU + store ----
    size_t ob = (size_t)gw * F + lane * FPL;
#pragma unroll
    for (int i = 0; i < FPL; i++) {
        float v = acc[i] + bias[lane * FPL + i];
        if (apply_elu) v = (v > 0.f) ? v : expm1f(v);
        if (out_h) out_h[ob + i] = __float2half_rn(v);
        else out[ob + i] = v;
    }
}

// ---------------- launcher ----------------
extern "C" void kernel_launch(void* const* d_in, const int* in_sizes, int n_in,
                              void* d_out, int out_size) {
    const float* x   = (const float*)d_in[0];
    const int*   ei  = (const int*)d_in[1];
    const float* W1  = (const float*)d_in[2];
    const float* as1 = (const float*)d_in[3];
    const float* ad1 = (const float*)d_in[4];
    const float* b1  = (const float*)d_in[5];
    const float* W2  = (const float*)d_in[6];
    const float* as2 = (const float*)d_in[7];
    const float* ad2 = (const float*)d_in[8];
    const float* b2  = (const float*)d_in[9];
    const float* W3  = (const float*)d_in[10];
    const float* as3 = (const float*)d_in[11];
    const float* ad3 = (const float*)d_in[12];
    const float* b3  = (const float*)d_in[13];
    float* out = (float*)d_out;

    int n = in_sizes[0] / 256;   // 50000
    int e = in_sizes[1] / 2;     // 320000

    __half *bufA, *bufB, *xh, *w1h, *w2h, *w3h;
    cudaGetSymbolAddress((void**)&bufA, g_bufAh);
    cudaGetSymbolAddress((void**)&bufB, g_bufBh);
    cudaGetSymbolAddress((void**)&xh, g_xh);
    cudaGetSymbolAddress((void**)&w1h, g_w1h);
    cudaGetSymbolAddress((void**)&w2h, g_w2h);
    cudaGetSymbolAddress((void**)&w3h, g_w3h);

    int nb1 = (n + 1023) / 1024;
    int nrb = (n + 127) / 128;
    int nab = (n + 7) / 8;

    // side stream for weight-convert + CSR build, overlapped with x-convert +
    // layer-1 GEMM on the default stream.
    cudaStream_t s2;
    cudaStreamCreateWithFlags(&s2, cudaStreamNonBlocking);
    cudaEvent_t ev1, ev0, ev2;
    cudaEventCreateWithFlags(&ev1, cudaEventDisableTiming);
    cudaEventCreateWithFlags(&ev0, cudaEventDisableTiming);
    cudaEventCreateWithFlags(&ev2, cudaEventDisableTiming);

    cudaEventRecord(ev1, 0);
    cudaStreamWaitEvent(s2, ev1, 0);

    // submission order matters for the ncu capture slot (#4 = layer-1 GEMM)
    // 1 (s2): weight conversion
    k_prew<<<64, 256, 0, s2>>>(W1, W2, W3, in_sizes[2], in_sizes[6], in_sizes[10]);
    cudaEventRecord(ev0, s2);
    // 2 (s0): x conversion
    k_prex<<<512, 256>>>(x, in_sizes[0] / 4);
    // 3 (s2): CSR init
    k_init<<<(n + 255) / 256, 256, 0, s2>>>(n);
    // 4 (s0): layer-1 GEMM  <-- capture slot
    cudaStreamWaitEvent(0, ev0, 0);
    k_gemm_tc<<<dim3(2, nrb), 256>>>(xh, w1h, bufA, as1, ad1, n, 256, 256);
    // 5..8 (s2): rest of CSR build
    k_count<<<(e + 255) / 256, 256, 0, s2>>>(ei, e);
    k_scan1<<<nb1, 1024, 0, s2>>>(n);
    k_scan3m<<<nb1, 1024, 0, s2>>>(n);
    k_scatter<<<(e + n + 255) / 256, 256, 0, s2>>>(ei, e, n);
    cudaEventRecord(ev2, s2);

    // join: aggregation needs both GEMM-1 and CSR
    cudaStreamWaitEvent(0, ev2, 0);

    k_agg_w<256, 4><<<nab, 256>>>(bufA, b1, nullptr, bufB, n, 1);
    k_gemm_tc<<<dim3(2, nrb), 256>>>(bufB, w2h, bufA, as2, ad2, n, 256, 256);
    k_agg_w<256, 4><<<nab, 256>>>(bufA, b2, nullptr, bufB, n, 1);
    k_gemm_tc<<<dim3(1, nrb), 256>>>(bufB, w3h, bufA, as3, ad3, n, 256, 64);
    k_agg_w<64, 1><<<nab, 256>>>(bufA, b3, out, nullptr, n, 0);
}

// round 9
// speedup vs baseline: 3.9433x; 1.0169x over previous
#include <cuda_runtime.h>
#include <cuda_fp16.h>
#include <math.h>
#include <stdint.h>

// ---------------- static scratch (no allocation allowed) ----------------
#define N_CAP 65536
#define E_CAP (1 << 20)

__device__ __half g_bufA[(size_t)N_CAP * 256];
__device__ __half g_bufB[(size_t)N_CAP * 256];
__device__ __half g_bufC[(size_t)N_CAP * 256];
__device__ __half g_xh[(size_t)N_CAP * 256];
__device__ __half g_w1h[65536];
__device__ __half g_w2h[65536];
__device__ __half g_w3h[16384];
__device__ float g_alsL[3 * N_CAP * 4];   // per-layer attention logits (src part)
__device__ float g_aldL[3 * N_CAP * 4];   // per-layer attention logits (dst part)
__device__ int   g_rowptr[N_CAP + 1];
__device__ int   g_wptr[N_CAP];
__device__ int   g_srcs[E_CAP];
__device__ int   g_bsum[80];

// ---------------- preconvert ----------------
__global__ void k_prew(const float* __restrict__ W1, const float* __restrict__ W2,
                       const float* __restrict__ W3, int nw1, int nw2, int nw3) {
    int i = blockIdx.x * blockDim.x + threadIdx.x;
    int stride = gridDim.x * blockDim.x;
    for (int j = i; j < nw1; j += stride) g_w1h[j] = __float2half_rn(W1[j]);
    for (int j = i; j < nw2; j += stride) g_w2h[j] = __float2half_rn(W2[j]);
    for (int j = i; j < nw3; j += stride) g_w3h[j] = __float2half_rn(W3[j]);
}

__global__ void k_prex(const float* __restrict__ x, int nx4) {
    int i = blockIdx.x * blockDim.x + threadIdx.x;
    int stride = gridDim.x * blockDim.x;
    const float4* x4 = (const float4*)x;
    uint2* xo = (uint2*)g_xh;
    for (int j = i; j < nx4; j += stride) {
        float4 v = x4[j];
        __half2 lo = __floats2half2_rn(v.x, v.y);
        __half2 hi = __floats2half2_rn(v.z, v.w);
        uint2 o;
        o.x = *(uint32_t*)&lo;
        o.y = *(uint32_t*)&hi;
        xo[j] = o;
    }
}

// ---------------- CSR build ----------------
__global__ void k_init(int n) {
    int i = blockIdx.x * blockDim.x + threadIdx.x;
    if (i < n) g_wptr[i] = 1;  // self-loop pre-count
}

__global__ void k_count(const int* __restrict__ ei, int e) {
    int t = blockIdx.x * blockDim.x + threadIdx.x;
    if (t < e) atomicAdd(&g_wptr[ei[e + t]], 1);
}

__global__ void k_scan1(int n) {
    __shared__ int sm[1024];
    int t = threadIdx.x;
    int i = blockIdx.x * 1024 + t;
    int v = (i < n) ? g_wptr[i] : 0;
    sm[t] = v;
    __syncthreads();
    for (int off = 1; off < 1024; off <<= 1) {
        int x = (t >= off) ? sm[t - off] : 0;
        __syncthreads();
        sm[t] += x;
        __syncthreads();
    }
    if (i < n) g_rowptr[i + 1] = sm[t];
    if (t == 1023) g_bsum[blockIdx.x] = sm[1023];
}

__global__ void k_scan3m(int n) {
    __shared__ int s_off;
    int t = threadIdx.x, b = blockIdx.x;
    if (t < 32) {
        int acc = 0;
        for (int i = t; i < b; i += 32) acc += g_bsum[i];
#pragma unroll
        for (int o = 16; o; o >>= 1) acc += __shfl_down_sync(0xffffffffu, acc, o);
        if (t == 0) s_off = acc;
    }
    __syncthreads();
    int i = b * 1024 + t;
    if (i < n) {
        int v = g_rowptr[i + 1] + s_off;
        g_rowptr[i + 1] = v;
        if (i + 1 < n) g_wptr[i + 1] = v;
    }
    if (i == 0) { g_rowptr[0] = 0; g_wptr[0] = 0; }
}

__global__ void k_scatter(const int* __restrict__ ei, int e, int n) {
    int t = blockIdx.x * blockDim.x + threadIdx.x;
    if (t < e) {
        int src = ei[t];
        int dst = ei[e + t];
        int pos = atomicAdd(&g_wptr[dst], 1);
        g_srcs[pos] = src;
    } else if (t < e + n) {
        int i = t - e;
        int pos = atomicAdd(&g_wptr[i], 1);
        g_srcs[pos] = i;  // self loop
    }
}

// ---------------- cp.async / ldmatrix helpers ----------------
__device__ __forceinline__ void cp16(uint32_t dst, const void* src, int bytes) {
    asm volatile("cp.async.cg.shared.global [%0], [%1], 16, %2;"
                 :: "r"(dst), "l"(src), "r"(bytes));
}
__device__ __forceinline__ void cp_commit() { asm volatile("cp.async.commit_group;"); }
template <int NN> __device__ __forceinline__ void cp_wait() {
    asm volatile("cp.async.wait_group %0;" :: "n"(NN));
}
__device__ __forceinline__ void ldm4(uint32_t& r0, uint32_t& r1, uint32_t& r2,
                                     uint32_t& r3, uint32_t addr) {
    asm volatile("ldmatrix.sync.aligned.m8n8.x4.shared.b16 {%0,%1,%2,%3}, [%4];"
                 : "=r"(r0), "=r"(r1), "=r"(r2), "=r"(r3) : "r"(addr));
}
__device__ __forceinline__ void ldm4t(uint32_t& r0, uint32_t& r1, uint32_t& r2,
                                      uint32_t& r3, uint32_t addr) {
    asm volatile("ldmatrix.sync.aligned.m8n8.x4.trans.shared.b16 {%0,%1,%2,%3}, [%4];"
                 : "=r"(r0), "=r"(r1), "=r"(r2), "=r"(r3) : "r"(addr));
}

// ---------------- fp16 tensor-core GEMM + fused attention logits ----------------
// C[rows of n, M] = A @ B, fp16 in/out, fp32 acc. Tile 128x128, BK=32.
// 8 warps 4x2, warp tile 32x64, mma m16n8k16 via ldmatrix. row_base selects
// the row slice (for split-half pipelining). ONE __syncthreads per K-iter.
#define ASTR 40
#define BSTR 136

__global__ __launch_bounds__(256, 2) void k_gemm_tc(const __half* __restrict__ A,
                                                    const __half* __restrict__ B,
                                                    __half* __restrict__ C,
                                                    const float* __restrict__ a_s,
                                                    const float* __restrict__ a_d,
                                                    float* __restrict__ o_als,
                                                    float* __restrict__ o_ald,
                                                    int row_base, int n, int K, int M) {
    __shared__ __half As[2][128][ASTR];
    __shared__ __half Bs[2][32][BSTR];
    __shared__ float s_als[128][2], s_ald[128][2];
    __shared__ float s_as[128], s_ad[128];

    int tid = threadIdx.x, lane = tid & 31, warp = tid >> 5;
    int wm = warp >> 1, wn = warp & 1;
    int r0 = row_base + blockIdx.y * 128, c0 = blockIdx.x * 128;

    uint32_t as_base = (uint32_t)__cvta_generic_to_shared(&As[0][0][0]);
    uint32_t bs_base = (uint32_t)__cvta_generic_to_shared(&Bs[0][0][0]);

    if (tid < 128 && c0 + tid < M) {
        s_as[tid] = a_s[c0 + tid];
        s_ad[tid] = a_d[c0 + tid];
    }

    float acc[2][8][4];
#pragma unroll
    for (int mt = 0; mt < 2; mt++)
#pragma unroll
        for (int nt = 0; nt < 8; nt++)
#pragma unroll
            for (int i = 0; i < 4; i++) acc[mt][nt][i] = 0.f;

    int KT = K >> 5;

#define LOAD_TILE(KT_IDX, BUF)                                                      \
    {                                                                               \
        int k0 = (KT_IDX) << 5;                                                     \
        _Pragma("unroll")                                                           \
        for (int i = 0; i < 2; i++) {                                               \
            int row = (tid >> 2) + 64 * i;                                          \
            int ac = (tid & 3) * 8;                                                 \
            int gr = r0 + row;                                                      \
            const __half* src = A + (size_t)(gr < n ? gr : 0) * K + k0 + ac;        \
            cp16(as_base + ((BUF) * 128 + row) * (ASTR * 2) + ac * 2, src,          \
                 gr < n ? 16 : 0);                                                  \
        }                                                                           \
        _Pragma("unroll")                                                           \
        for (int i = 0; i < 2; i++) {                                               \
            int rr = (tid >> 4) + 16 * i;                                           \
            int bc = (tid & 15) * 8;                                                \
            int gc = c0 + bc;                                                       \
            const __half* src = B + (size_t)(k0 + rr) * M + (gc < M ? gc : 0);      \
            cp16(bs_base + ((BUF) * 32 + rr) * (BSTR * 2) + bc * 2, src,            \
                 gc < M ? 16 : 0);                                                  \
        }                                                                           \
    }

    LOAD_TILE(0, 0);
    cp_commit();

    for (int kt = 0; kt < KT; kt++) {
        int buf = kt & 1;
        cp_wait<0>();
        __syncthreads();   // buf visible; all done reading buf^1 from prev iter
        if (kt + 1 < KT) {
            LOAD_TILE(kt + 1, buf ^ 1);
            cp_commit();
        }

#pragma unroll
        for (int ks = 0; ks < 2; ks++) {
            int kb = ks * 16;
            uint32_t a[2][4], b[8][2];
#pragma unroll
            for (int mt = 0; mt < 2; mt++) {
                int row = wm * 32 + mt * 16 + (lane & 15);
                int col = kb + ((lane & 16) ? 8 : 0);
                uint32_t addr = as_base + (buf * 128 + row) * (ASTR * 2) + col * 2;
                ldm4(a[mt][0], a[mt][1], a[mt][2], a[mt][3], addr);
            }
#pragma unroll
            for (int g = 0; g < 4; g++) {
                int row = kb + (lane & 15);
                int col = wn * 64 + g * 16 + ((lane & 16) ? 8 : 0);
                uint32_t addr = bs_base + (buf * 32 + row) * (BSTR * 2) + col * 2;
                ldm4t(b[g * 2][0], b[g * 2][1], b[g * 2 + 1][0], b[g * 2 + 1][1], addr);
            }
#pragma unroll
            for (int mt = 0; mt < 2; mt++)
#pragma unroll
                for (int nt = 0; nt < 8; nt++) {
                    asm volatile(
                        "mma.sync.aligned.m16n8k16.row.col.f32.f16.f16.f32 "
                        "{%0,%1,%2,%3}, {%4,%5,%6,%7}, {%8,%9}, {%0,%1,%2,%3};"
                        : "+f"(acc[mt][nt][0]), "+f"(acc[mt][nt][1]),
                          "+f"(acc[mt][nt][2]), "+f"(acc[mt][nt][3])
                        : "r"(a[mt][0]), "r"(a[mt][1]), "r"(a[mt][2]), "r"(a[mt][3]),
                          "r"(b[nt][0]), "r"(b[nt][1]));
                }
        }
    }

    // ---- fused attention-logit epilogue + C store (fp16) ----
    bool colok = (c0 + wn * 64) < M;
    if (colok) {
#pragma unroll
        for (int mt = 0; mt < 2; mt++) {
#pragma unroll
            for (int rr = 0; rr < 2; rr++) {
                float ps = 0.f, pd = 0.f;
#pragma unroll
                for (int nt = 0; nt < 8; nt++)
#pragma unroll
                    for (int q = 0; q < 2; q++) {
                        int lc = nt * 8 + (lane & 3) * 2 + q;
                        float v = acc[mt][nt][rr * 2 + q];
                        ps = fmaf(v, s_as[wn * 64 + lc], ps);
                        pd = fmaf(v, s_ad[wn * 64 + lc], pd);
                    }
                ps += __shfl_down_sync(0xffffffffu, ps, 1);
                ps += __shfl_down_sync(0xffffffffu, ps, 2);
                pd += __shfl_down_sync(0xffffffffu, pd, 1);
                pd += __shfl_down_sync(0xffffffffu, pd, 2);
                if ((lane & 3) == 0) {
                    int rl = wm * 32 + mt * 16 + (lane >> 2) + rr * 8;
                    s_als[rl][wn] = ps;
                    s_ald[rl][wn] = pd;
                }
            }
        }
#pragma unroll
        for (int mt = 0; mt < 2; mt++) {
            int row = r0 + wm * 32 + mt * 16 + (lane >> 2);
#pragma unroll
            for (int nt = 0; nt < 8; nt++) {
                int col = c0 + wn * 64 + nt * 8 + (lane & 3) * 2;
                if (row < n) {
                    __half2 v = __floats2half2_rn(acc[mt][nt][0], acc[mt][nt][1]);
                    *(uint32_t*)&C[(size_t)row * M + col] = *(uint32_t*)&v;
                }
                if (row + 8 < n) {
                    __half2 v = __floats2half2_rn(acc[mt][nt][2], acc[mt][nt][3]);
                    *(uint32_t*)&C[(size_t)(row + 8) * M + col] = *(uint32_t*)&v;
                }
            }
        }
    }
    __syncthreads();

    if (tid < 128) {
        int row = r0 + tid;
        if (row < n) {
            int hb = c0 >> 6;
            o_als[row * 4 + hb] = s_als[tid][0];
            o_ald[row * 4 + hb] = s_ald[tid][0];
            if (c0 + 64 < M) {
                o_als[row * 4 + hb + 1] = s_als[tid][1];
                o_ald[row * 4 + hb + 1] = s_ald[tid][1];
            }
        }
    }
}

// ---------------- aggregation: one WARP per dst node (fp16 features) ----------------
template <int F, int H>
__global__ __launch_bounds__(256) void k_agg_w(const __half* __restrict__ h,
                                               const float* __restrict__ bias,
                                               float* __restrict__ out,
                                               __half* __restrict__ out_h,
                                               const float* __restrict__ als,
                                               const float* __restrict__ ald_g,
                                               int base, int cnt, int n, int apply_elu) {
    int gw = base + ((blockIdx.x * 256 + threadIdx.x) >> 5);
    int lane = threadIdx.x & 31;
    if (gw >= base + cnt || gw >= n) return;
    constexpr int FPL = F / 32;
    constexpr int CH = F / H;
    int hh = (lane * FPL) / CH;

    int r0 = g_rowptr[gw];
    int deg = g_rowptr[gw + 1] - r0;

    float4 aldv = *(const float4*)&ald_g[gw * 4];
    float ald[4] = {aldv.x, aldv.y, aldv.z, aldv.w};

    // ---- online softmax stats ----
    float m[H], sa[H];
#pragma unroll
    for (int i = 0; i < H; i++) { m[i] = -1e30f; sa[i] = 0.f; }
    for (int j = lane; j < deg; j += 32) {
        int src = __ldg(&g_srcs[r0 + j]);
        float4 alv = *(const float4*)&als[src * 4];
        float al[4] = {alv.x, alv.y, alv.z, alv.w};
#pragma unroll
        for (int i = 0; i < H; i++) {
            float l = al[i] + ald[i];
            l = (l < 0.f) ? 0.2f * l : l;
            float nm = fmaxf(m[i], l);
            sa[i] = sa[i] * __expf(m[i] - nm) + __expf(l - nm);
            m[i] = nm;
        }
    }
#pragma unroll
    for (int o = 16; o; o >>= 1) {
#pragma unroll
        for (int i = 0; i < H; i++) {
            float mo = __shfl_xor_sync(0xffffffffu, m[i], o);
            float so = __shfl_xor_sync(0xffffffffu, sa[i], o);
            float nm = fmaxf(m[i], mo);
            sa[i] = sa[i] * __expf(m[i] - nm) + so * __expf(mo - nm);
            m[i] = nm;
        }
    }
    float mh = m[hh];
    float invh = 1.f / (sa[hh] + 1e-16f);
    float aldh = ald[hh];

    // ---- weighted feature gather (fp16 loads, unrolled x2) ----
    float acc[FPL];
#pragma unroll
    for (int i = 0; i < FPL; i++) acc[i] = 0.f;

    for (int eb = 0; eb < deg; eb += 32) {
        int ecnt = min(32, deg - eb);
        int mysrc = (eb + lane < deg) ? g_srcs[r0 + eb + lane] : 0;
        int jj = 0;
        for (; jj + 2 <= ecnt; jj += 2) {
            int s0 = __shfl_sync(0xffffffffu, mysrc, jj);
            int s1 = __shfl_sync(0xffffffffu, mysrc, jj + 1);
            float l0 = als[s0 * 4 + hh] + aldh;
            float l1 = als[s1 * 4 + hh] + aldh;
            l0 = (l0 < 0.f) ? 0.2f * l0 : l0;
            l1 = (l1 < 0.f) ? 0.2f * l1 : l1;
            float a0 = __expf(l0 - mh) * invh;
            float a1 = __expf(l1 - mh) * invh;
            const __half* h0 = h + (size_t)s0 * F + lane * FPL;
            const __half* h1 = h + (size_t)s1 * F + lane * FPL;
            if (FPL == 8) {
                uint4 u = *(const uint4*)h0;
                uint4 w = *(const uint4*)h1;
                const __half2* uh = (const __half2*)&u;
                const __half2* wh = (const __half2*)&w;
#pragma unroll
                for (int q = 0; q < 4; q++) {
                    float2 uf = __half22float2(uh[q]);
                    float2 wf = __half22float2(wh[q]);
                    acc[q * 2 + 0] = fmaf(a0, uf.x, fmaf(a1, wf.x, acc[q * 2 + 0]));
                    acc[q * 2 + 1] = fmaf(a0, uf.y, fmaf(a1, wf.y, acc[q * 2 + 1]));
                }
            } else {
                float2 uf = __half22float2(*(const __half2*)h0);
                float2 wf = __half22float2(*(const __half2*)h1);
                acc[0] = fmaf(a0, uf.x, fmaf(a1, wf.x, acc[0]));
                acc[1] = fmaf(a0, uf.y, fmaf(a1, wf.y, acc[1]));
            }
        }
        if (jj < ecnt) {
            int s0 = __shfl_sync(0xffffffffu, mysrc, jj);
            float l0 = als[s0 * 4 + hh] + aldh;
            l0 = (l0 < 0.f) ? 0.2f * l0 : l0;
            float a0 = __expf(l0 - mh) * invh;
            const __half* h0 = h + (size_t)s0 * F + lane * FPL;
            if (FPL == 8) {
                uint4 u = *(const uint4*)h0;
                const __half2* uh = (const __half2*)&u;
#pragma unroll
                for (int q = 0; q < 4; q++) {
                    float2 uf = __half22float2(uh[q]);
                    acc[q * 2 + 0] = fmaf(a0, uf.x, acc[q * 2 + 0]);
                    acc[q * 2 + 1] = fmaf(a0, uf.y, acc[q * 2 + 1]);
                }
            } else {
                float2 uf = __half22float2(*(const __half2*)h0);
                acc[0] = fmaf(a0, uf.x, acc[0]);
                acc[1] = fmaf(a0, uf.y, acc[1]);
            }
        }
    }

    // ---- bias + ELU + store ----
    size_t ob = (size_t)gw * F + lane * FPL;
#pragma unroll
    for (int i = 0; i < FPL; i++) {
        float v = acc[i] + bias[lane * FPL + i];
        if (apply_elu) v = (v > 0.f) ? v : expm1f(v);
        if (out_h) out_h[ob + i] = __float2half_rn(v);
        else out[ob + i] = v;
    }
}

// ---------------- launcher ----------------
extern "C" void kernel_launch(void* const* d_in, const int* in_sizes, int n_in,
                              void* d_out, int out_size) {
    const float* x   = (const float*)d_in[0];
    const int*   ei  = (const int*)d_in[1];
    const float* W1  = (const float*)d_in[2];
    const float* as1 = (const float*)d_in[3];
    const float* ad1 = (const float*)d_in[4];
    const float* b1  = (const float*)d_in[5];
    const float* W2  = (const float*)d_in[6];
    const float* as2 = (const float*)d_in[7];
    const float* ad2 = (const float*)d_in[8];
    const float* b2  = (const float*)d_in[9];
    const float* W3  = (const float*)d_in[10];
    const float* as3 = (const float*)d_in[11];
    const float* ad3 = (const float*)d_in[12];
    const float* b3  = (const float*)d_in[13];
    float* out = (float*)d_out;

    int n = in_sizes[0] / 256;   // 50000
    int e = in_sizes[1] / 2;     // 320000

    __half *bufA, *bufB, *bufC, *xh, *w1h, *w2h, *w3h;
    float *alsL, *aldL;
    cudaGetSymbolAddress((void**)&bufA, g_bufA);
    cudaGetSymbolAddress((void**)&bufB, g_bufB);
    cudaGetSymbolAddress((void**)&bufC, g_bufC);
    cudaGetSymbolAddress((void**)&xh, g_xh);
    cudaGetSymbolAddress((void**)&w1h, g_w1h);
    cudaGetSymbolAddress((void**)&w2h, g_w2h);
    cudaGetSymbolAddress((void**)&w3h, g_w3h);
    cudaGetSymbolAddress((void**)&alsL, g_alsL);
    cudaGetSymbolAddress((void**)&aldL, g_aldL);
    float* als1 = alsL;                 float* ald1 = aldL;
    float* als2 = alsL + N_CAP * 4;     float* ald2 = aldL + N_CAP * 4;
    float* als3 = alsL + 2 * N_CAP * 4; float* ald3 = aldL + 2 * N_CAP * 4;

    int nb1 = (n + 1023) / 1024;
    int nrb = (n + 127) / 128;

    // split point for half-pipelining (multiple of 128)
    int nh = ((n / 2 + 127) / 128) * 128;
    if (nh > n) nh = n;
    int rb = n - nh;                      // rows in half b
    int ya = nh / 128, yb = (rb + 127) / 128;
    int aga = (nh + 7) / 8, agb = (rb + 7) / 8;

    cudaStream_t s2;
    cudaStreamCreateWithFlags(&s2, cudaStreamNonBlocking);
    cudaEvent_t evS, evW, evG1, evCSR, evG2a, evG2b, evG3a, evG3b, evEnd;
    cudaEventCreateWithFlags(&evS, cudaEventDisableTiming);
    cudaEventCreateWithFlags(&evW, cudaEventDisableTiming);
    cudaEventCreateWithFlags(&evG1, cudaEventDisableTiming);
    cudaEventCreateWithFlags(&evCSR, cudaEventDisableTiming);
    cudaEventCreateWithFlags(&evG2a, cudaEventDisableTiming);
    cudaEventCreateWithFlags(&evG2b, cudaEventDisableTiming);
    cudaEventCreateWithFlags(&evG3a, cudaEventDisableTiming);
    cudaEventCreateWithFlags(&evG3b, cudaEventDisableTiming);
    cudaEventCreateWithFlags(&evEnd, cudaEventDisableTiming);

    cudaEventRecord(evS, 0);
    cudaStreamWaitEvent(s2, evS, 0);

    // 1 (s2): weight conversion
    k_prew<<<64, 256, 0, s2>>>(W1, W2, W3, in_sizes[2], in_sizes[6], in_sizes[10]);
    cudaEventRecord(evW, s2);
    // 2 (s0): x conversion
    k_prex<<<512, 256>>>(x, in_sizes[0] / 4);
    // 3 (s2): CSR init
    k_init<<<(n + 255) / 256, 256, 0, s2>>>(n);
    // 4 (s0): layer-1 GEMM (full)  <-- ncu capture slot
    cudaStreamWaitEvent(0, evW, 0);
    k_gemm_tc<<<dim3(2, nrb), 256>>>(xh, w1h, bufA, as1, ad1, als1, ald1, 0, n, 256, 256);
    cudaEventRecord(evG1, 0);
    // (s2): rest of CSR
    k_count<<<(e + 255) / 256, 256, 0, s2>>>(ei, e);
    k_scan1<<<nb1, 1024, 0, s2>>>(n);
    k_scan3m<<<nb1, 1024, 0, s2>>>(n);
    k_scatter<<<(e + n + 255) / 256, 256, 0, s2>>>(ei, e, n);
    cudaEventRecord(evCSR, s2);

    // ---- layer 1 aggregation, split halves ----
    cudaStreamWaitEvent(0, evCSR, 0);
    k_agg_w<256, 4><<<aga, 256>>>(bufA, b1, nullptr, bufB, als1, ald1, 0, nh, n, 1);
    cudaStreamWaitEvent(s2, evG1, 0);
    k_agg_w<256, 4><<<agb, 256, 0, s2>>>(bufA, b1, nullptr, bufB, als1, ald1, nh, rb, n, 1);

    // ---- layer 2 GEMM halves (a overlaps agg1b) ----
    k_gemm_tc<<<dim3(2, ya), 256>>>(bufB, w2h, bufC, as2, ad2, als2, ald2, 0, n, 256, 256);
    cudaEventRecord(evG2a, 0);
    k_gemm_tc<<<dim3(2, yb), 256, 0, s2>>>(bufB, w2h, bufC, as2, ad2, als2, ald2, nh, n, 256, 256);
    cudaEventRecord(evG2b, s2);

    // ---- layer 2 aggregation halves ----
    cudaStreamWaitEvent(0, evG2b, 0);
    k_agg_w<256, 4><<<aga, 256>>>(bufC, b2, nullptr, bufA, als2, ald2, 0, nh, n, 1);
    cudaStreamWaitEvent(s2, evG2a, 0);
    k_agg_w<256, 4><<<agb, 256, 0, s2>>>(bufC, b2, nullptr, bufA, als2, ald2, nh, rb, n, 1);

    // ---- layer 3 GEMM halves (a overlaps agg2b) ----
    k_gemm_tc<<<dim3(1, ya), 256>>>(bufA, w3h, bufB, as3, ad3, als3, ald3, 0, n, 256, 64);
    cudaEventRecord(evG3a, 0);
    k_gemm_tc<<<dim3(1, yb), 256, 0, s2>>>(bufA, w3h, bufB, as3, ad3, als3, ald3, nh, n, 256, 64);
    cudaEventRecord(evG3b, s2);

    // ---- layer 3 aggregation halves -> output ----
    cudaStreamWaitEvent(0, evG3b, 0);
    k_agg_w<64, 1><<<aga, 256>>>(bufB, b3, out, nullptr, als3, ald3, 0, nh, n, 0);
    cudaStreamWaitEvent(s2, evG3a, 0);
    k_agg_w<64, 1><<<agb, 256, 0, s2>>>(bufB, b3, out, nullptr, als3, ald3, nh, rb, n, 0);
    cudaEventRecord(evEnd, s2);
    cudaStreamWaitEvent(0, evEnd, 0);
}